// round 12
// baseline (speedup 1.0000x reference)
#include <cuda_runtime.h>
#include <cuda_bf16.h>
#include <cstdint>

#define N_ATOMS   100000
#define N_BONDS   200000
#define MAX_NB    6
#define ATOM_FDIM 133
#define BOND_FDIM 147
#define HIDDEN    256
#define N_MOLS    4096
#define MOL_FEAT  200
#define FFNN_HID  512
#define ENC_HID   256

// K padded to multiple of 32 (chunk size)
#define KPAD_WI 160
#define KPAD_WO 416
#define KPAD_W1 480
#define KPAD_W2 512
#define XSTRIDE 512   // x buffer row stride (456 -> 512, zero filled)

// ---------------- scratch (static device globals; no allocation allowed) ----
__device__ float g_inputs[N_BONDS * HIDDEN];
__device__ float g_msgA  [N_BONDS * HIDDEN];
__device__ float g_msgB  [N_BONDS * HIDDEN];
__device__ float g_amsg  [N_ATOMS * HIDDEN];
__device__ float g_hid   [N_ATOMS * HIDDEN];
__device__ float g_x     [N_MOLS * XSTRIDE];
__device__ float g_h     [N_MOLS * FFNN_HID];

// split-bf16 weight buffers, layout [N][Kpad] (transposed, zero padded)
__device__ __nv_bfloat16 g_Wi_hi[HIDDEN  * KPAD_WI], g_Wi_lo[HIDDEN  * KPAD_WI];
__device__ __nv_bfloat16 g_Wh_hi[HIDDEN  * HIDDEN ], g_Wh_lo[HIDDEN  * HIDDEN ];
__device__ __nv_bfloat16 g_Wo_hi[HIDDEN  * KPAD_WO], g_Wo_lo[HIDDEN  * KPAD_WO];
__device__ __nv_bfloat16 g_W1_hi[FFNN_HID* KPAD_W1], g_W1_lo[FFNN_HID* KPAD_W1];
__device__ __nv_bfloat16 g_W2_hi[ENC_HID * KPAD_W2], g_W2_lo[ENC_HID * KPAD_W2];

// =================== PTX helpers (sm_80-level features only) ================
__device__ __forceinline__ uint32_t smem_u32(const void* p) {
    uint32_t a;
    asm("{ .reg .u64 t; cvta.to.shared.u64 t, %1; cvt.u32.u64 %0, t; }" : "=r"(a) : "l"(p));
    return a;
}
__device__ __forceinline__ void ldsm_x4(uint32_t* r, uint32_t addr) {
    asm volatile("ldmatrix.sync.aligned.m8n8.x4.shared.b16 {%0,%1,%2,%3}, [%4];"
                 : "=r"(r[0]), "=r"(r[1]), "=r"(r[2]), "=r"(r[3]) : "r"(addr));
}
__device__ __forceinline__ void mma16816(float* c, const uint32_t* a, uint32_t b0, uint32_t b1) {
    asm volatile("mma.sync.aligned.m16n8k16.row.col.f32.bf16.bf16.f32 "
                 "{%0,%1,%2,%3}, {%4,%5,%6,%7}, {%8,%9}, {%0,%1,%2,%3};"
                 : "+f"(c[0]), "+f"(c[1]), "+f"(c[2]), "+f"(c[3])
                 : "r"(a[0]), "r"(a[1]), "r"(a[2]), "r"(a[3]), "r"(b0), "r"(b1));
}
#define CP_ASYNC16(dst, src) \
    asm volatile("cp.async.cg.shared.global [%0], [%1], 16;" :: "r"(dst), "l"(src))
#define CP_COMMIT asm volatile("cp.async.commit_group;" ::: "memory")
#define CP_WAIT0  asm volatile("cp.async.wait_group 0;"  ::: "memory")

// 16B-slot swizzle: slot' = slot ^ ((row>>1)&3). Conflict-free for both the
// 8-row ldmatrix phases (even rows cover banks 0-15 with distinct slots, odd
// rows banks 16-31) and the 8-row x 4-seg staging stores.
__device__ __forceinline__ uint32_t sw_off(uint32_t row, uint32_t seg) {
    return row * 64u + ((seg ^ ((row >> 1) & 3u)) << 4);
}

// =================== tensor-core GEMM (mma.sync / HMMA), pipelined =========
// CTA: 256 thr, tile M=64 x N=128, K chunk 32. Split-bf16: hi*hi + lo*hi + hi*lo.
// Swizzled 64B smem rows -> 24.6KB/stage -> 4 CTAs/SM (32 warps).
enum GemmMode { MODE_PLAIN2 = 0, MODE_MSG = 1, MODE_CONCAT = 2, MODE_BIAS = 3 };

#define A_ROWS   64
#define B_ROWS   128
#define OFF_I1   0
#define OFF_I2   256
#define STG_A_LO (A_ROWS * 64)                   // 4096
#define STG_B_HI (2 * A_ROWS * 64)               // 8192
#define STG_B_LO (STG_B_HI + B_ROWS * 64)        // 16384
#define STG_SZ   (STG_B_HI + 2 * B_ROWS * 64)    // 24576 bytes per stage
#define STG_BASE 1024
#define SMEM_TOT (STG_BASE + 2 * STG_SZ)         // 50176 bytes -> 4 CTAs/SM
#define NTHR 256

__device__ __forceinline__ void split_pack2(float x, float y, uint32_t& h, uint32_t& l) {
    __nv_bfloat16 hx = __float2bfloat16(x);
    __nv_bfloat16 hy = __float2bfloat16(y);
    __nv_bfloat16 lx = __float2bfloat16(x - __bfloat162float(hx));
    __nv_bfloat16 ly = __float2bfloat16(y - __bfloat162float(hy));
    h = (uint32_t)reinterpret_cast<unsigned short&>(hx) |
        ((uint32_t)reinterpret_cast<unsigned short&>(hy) << 16);
    l = (uint32_t)reinterpret_cast<unsigned short&>(lx) |
        ((uint32_t)reinterpret_cast<unsigned short&>(ly) << 16);
}

template<int MODE>
__device__ __forceinline__ void loadA_regs(float v[8], int gm, int kb, int M, int Ktrue,
                                           const float* __restrict__ A, int lda,
                                           const float* __restrict__ aux1,
                                           const float* __restrict__ aux2,
                                           int i1, int i2)
{
    if (MODE == MODE_MSG) {
        const float* p1 = aux1 + (size_t)i1 * HIDDEN + kb;
        const float* p2 = aux2 + (size_t)i2 * HIDDEN + kb;
        float4 a0 = *(const float4*)p1, a1 = *(const float4*)(p1 + 4);
        float4 b0 = *(const float4*)p2, b1 = *(const float4*)(p2 + 4);
        v[0]=a0.x-b0.x; v[1]=a0.y-b0.y; v[2]=a0.z-b0.z; v[3]=a0.w-b0.w;
        v[4]=a1.x-b1.x; v[5]=a1.y-b1.y; v[6]=a1.z-b1.z; v[7]=a1.w-b1.w;
    } else if (MODE == MODE_CONCAT) {
        #pragma unroll
        for (int j = 0; j < 8; ++j) {
            const int gk = kb + j;
            float x = 0.f;
            if (gm < M) {
                if (gk < ATOM_FDIM)               x = aux1[(size_t)gm * ATOM_FDIM + gk];
                else if (gk < ATOM_FDIM + HIDDEN) x = aux2[(size_t)gm * HIDDEN + (gk - ATOM_FDIM)];
            }
            v[j] = x;
        }
    } else if (MODE == MODE_BIAS) {
        const float* p = A + (size_t)gm * lda + kb;   // M multiple of 64, lda aligned
        float4 a0 = *(const float4*)p, a1 = *(const float4*)(p + 4);
        v[0]=a0.x; v[1]=a0.y; v[2]=a0.z; v[3]=a0.w;
        v[4]=a1.x; v[5]=a1.y; v[6]=a1.z; v[7]=a1.w;
    } else {  // MODE_PLAIN2 (f_bonds: ragged rows, unaligned stride)
        #pragma unroll
        for (int j = 0; j < 8; ++j) {
            const int gk = kb + j;
            v[j] = (gm < M && gk < Ktrue) ? A[(size_t)gm * lda + gk] : 0.f;
        }
    }
}

__device__ __forceinline__ void storeA_sm(char* smc, uint32_t stg, int arow, int aseg,
                                          const float v[8])
{
    uint32_t h[4], l[4];
    split_pack2(v[0], v[1], h[0], l[0]);
    split_pack2(v[2], v[3], h[1], l[1]);
    split_pack2(v[4], v[5], h[2], l[2]);
    split_pack2(v[6], v[7], h[3], l[3]);
    const uint32_t so = sw_off((uint32_t)arow, (uint32_t)aseg);
    *(uint4*)(smc + stg + so)            = make_uint4(h[0], h[1], h[2], h[3]);
    *(uint4*)(smc + stg + STG_A_LO + so) = make_uint4(l[0], l[1], l[2], l[3]);
}

__device__ __forceinline__ void loadB_cp(uint32_t sb_stg, const __nv_bfloat16* __restrict__ Bhi,
                                         const __nv_bfloat16* __restrict__ Blo,
                                         int n0, int Kpad, int k0, int tid)
{
    #pragma unroll
    for (int it = 0; it < 2; ++it) {
        const int t   = tid + it * NTHR;
        const int row = t >> 2, seg = t & 3;
        const size_t src = (size_t)(n0 + row) * Kpad + k0 + seg * 8;
        const uint32_t dst = sb_stg + STG_B_HI + sw_off((uint32_t)row, (uint32_t)seg);
        CP_ASYNC16(dst, Bhi + src);
        CP_ASYNC16(dst + (STG_B_LO - STG_B_HI), Blo + src);
    }
}

template<int MODE, int NCHUNKS>
__global__ __launch_bounds__(NTHR, 4)
void tgemm(const float* __restrict__ A, int lda,
           const __nv_bfloat16* __restrict__ Bhi, const __nv_bfloat16* __restrict__ Blo,
           int Kpad, int M, int Ntot, int Ktrue,
           float* __restrict__ C, float* __restrict__ C2,
           const float* __restrict__ ep,
           const int* __restrict__ idx1, const int* __restrict__ idx2,
           const float* __restrict__ aux1, const float* __restrict__ aux2)
{
    extern __shared__ char smc[];
    const uint32_t sb = smem_u32(smc);

    const int tid   = threadIdx.x;
    const int wid   = tid >> 5;
    const int lane  = tid & 31;
    const int warpM = wid & 1;          // 0..1 (M dir, 32 rows each)
    const int warpN = wid >> 1;         // 0..3 (N dir, 32 cols each)
    const int m0    = blockIdx.y * 64;
    const int n0    = blockIdx.x * 128;

    int* s_i1 = (int*)(smc + OFF_I1);
    int* s_i2 = (int*)(smc + OFF_I2);
    if (MODE == MODE_MSG && tid < 64) {
        int r = m0 + tid;
        s_i1[tid] = (r < M) ? idx1[r] : 0;
        s_i2[tid] = (r < M) ? idx2[r] : 0;
    }
    __syncthreads();

    const int arow_s = tid >> 2;        // staging A: row 0..63
    const int aseg   = tid & 3;         // seg 0..3 (8 elements each)
    const int gmA    = m0 + arow_s;
    int i1 = 0, i2 = 0;
    if (MODE == MODE_MSG) { i1 = s_i1[arow_s]; i2 = s_i2[arow_s]; }

    float acc[2][4][4];
    #pragma unroll
    for (int a = 0; a < 2; ++a)
        #pragma unroll
        for (int b = 0; b < 4; ++b)
            #pragma unroll
            for (int c = 0; c < 4; ++c) acc[a][b][c] = 0.f;

    // ---- prologue: stage chunk 0 into buffer 0 ----
    {
        loadB_cp(sb + STG_BASE, Bhi, Blo, n0, Kpad, 0, tid);
        CP_COMMIT;
        float v[8];
        loadA_regs<MODE>(v, gmA, aseg * 8, M, Ktrue, A, lda, aux1, aux2, i1, i2);
        storeA_sm(smc, STG_BASE, arow_s, aseg, v);
        CP_WAIT0;
        __syncthreads();
    }

    const uint32_t lrow = lane & 15;
    const uint32_t lkh  = (lane >> 4);          // 0..1: second 16B column

    #pragma unroll
    for (int ch = 0; ch < NCHUNKS; ++ch) {
        const int s = ch & 1;
        const uint32_t cur = STG_BASE + s * STG_SZ;
        const uint32_t nxt = STG_BASE + (s ^ 1) * STG_SZ;
        const bool more = (ch + 1 < NCHUNKS);   // compile-time after unroll

        // ---- prefetch next chunk: B via cp.async, A into registers ----
        float vn[8];
        if (more) {
            loadB_cp(sb + nxt, Bhi, Blo, n0, Kpad, (ch + 1) * 32, tid);
            CP_COMMIT;
            loadA_regs<MODE>(vn, gmA, (ch + 1) * 32 + aseg * 8, M, Ktrue,
                             A, lda, aux1, aux2, i1, i2);
        }

        // ---- compute on current stage: 2 x k16 ----
        #pragma unroll
        for (int kh = 0; kh < 2; ++kh) {
            const uint32_t segA = kh * 2 + lkh;   // 16B-slot index 0..3

            uint32_t ah[2][4], al[2][4];
            #pragma unroll
            for (int mt = 0; mt < 2; ++mt) {
                const uint32_t ao = sw_off(warpM * 32 + mt * 16 + lrow, segA);
                ldsm_x4(ah[mt], sb + cur + ao);
                ldsm_x4(al[mt], sb + cur + STG_A_LO + ao);
            }
            #pragma unroll
            for (int np = 0; np < 2; ++np) {
                const uint32_t bo = sw_off(warpN * 32 + np * 16 + lrow, segA);
                uint32_t b[4];
                // pass 1+2 use B_hi; pass 3 reuses the same regs for B_lo
                ldsm_x4(b, sb + cur + STG_B_HI + bo);
                #pragma unroll
                for (int mt = 0; mt < 2; ++mt) {
                    mma16816(acc[mt][2*np    ], ah[mt], b[0], b[2]);
                    mma16816(acc[mt][2*np + 1], ah[mt], b[1], b[3]);
                }
                #pragma unroll
                for (int mt = 0; mt < 2; ++mt) {
                    mma16816(acc[mt][2*np    ], al[mt], b[0], b[2]);
                    mma16816(acc[mt][2*np + 1], al[mt], b[1], b[3]);
                }
                ldsm_x4(b, sb + cur + STG_B_LO + bo);
                #pragma unroll
                for (int mt = 0; mt < 2; ++mt) {
                    mma16816(acc[mt][2*np    ], ah[mt], b[0], b[2]);
                    mma16816(acc[mt][2*np + 1], ah[mt], b[1], b[3]);
                }
            }
        }

        // ---- finish staging next chunk ----
        if (more) {
            storeA_sm(smc, nxt, arow_s, aseg, vn);
            CP_WAIT0;
            __syncthreads();
        }
    }

    // ---- epilogue: direct accumulator stores with fused ops ----
    const int gi = lane >> 2;    // 0..7
    const int qi = lane & 3;     // 0..3
    #pragma unroll
    for (int mt = 0; mt < 2; ++mt) {
        const int row0 = m0 + warpM * 32 + mt * 16 + gi;
        #pragma unroll
        for (int nt = 0; nt < 4; ++nt) {
            const int gn = n0 + warpN * 32 + nt * 8 + qi * 2;
            const float* c = acc[mt][nt];
            #pragma unroll
            for (int half = 0; half < 2; ++half) {
                const int gm = row0 + half * 8;
                if (gm >= M) continue;
                const float u0 = c[2 * half], u1 = c[2 * half + 1];
                const size_t co = (size_t)gm * Ntot + gn;
                if (MODE == MODE_PLAIN2) {
                    *(float2*)(C  + co) = make_float2(u0, u1);
                    *(float2*)(C2 + co) = make_float2(fmaxf(u0, 0.f), fmaxf(u1, 0.f));
                } else if (MODE == MODE_MSG) {
                    const float2 e = *(const float2*)(ep + co);
                    *(float2*)(C + co) = make_float2(fmaxf(u0 + e.x, 0.f), fmaxf(u1 + e.y, 0.f));
                } else {
                    const float2 e = *(const float2*)(ep + gn);
                    *(float2*)(C + co) = make_float2(fmaxf(u0 + e.x, 0.f), fmaxf(u1 + e.y, 0.f));
                }
            }
        }
    }
}

// ---------------- merged weight prep: ONE launch for all 5 weights ---------
__device__ __forceinline__ void prep_one(const float* __restrict__ W, int K, int N, int Kpad,
                                         __nv_bfloat16* __restrict__ hi,
                                         __nv_bfloat16* __restrict__ lo, int i)
{
    const int n = i / Kpad, k = i % Kpad;
    const float v = (k < K) ? W[(size_t)k * N + n] : 0.f;
    const __nv_bfloat16 h = __float2bfloat16(v);
    hi[i] = h;
    lo[i] = __float2bfloat16(v - __bfloat162float(h));
}

#define E_WI (HIDDEN  * KPAD_WI)                  // 40960
#define E_WH (HIDDEN  * HIDDEN)                   // 65536
#define E_WO (HIDDEN  * KPAD_WO)                  // 106496
#define E_W1 (FFNN_HID* KPAD_W1)                  // 245760
#define E_W2 (ENC_HID * KPAD_W2)                  // 131072
#define E_C1 (E_WI)
#define E_C2 (E_C1 + E_WH)
#define E_C3 (E_C2 + E_WO)
#define E_C4 (E_C3 + E_W1)
#define E_TOT (E_C4 + E_W2)                       // 589824

__global__ __launch_bounds__(256)
void prep_all_k(const float* __restrict__ Wi, const float* __restrict__ Wh,
                const float* __restrict__ Wo, const float* __restrict__ W1,
                const float* __restrict__ W2,
                __nv_bfloat16* __restrict__ wi_h, __nv_bfloat16* __restrict__ wi_l,
                __nv_bfloat16* __restrict__ wh_h, __nv_bfloat16* __restrict__ wh_l,
                __nv_bfloat16* __restrict__ wo_h, __nv_bfloat16* __restrict__ wo_l,
                __nv_bfloat16* __restrict__ w1_h, __nv_bfloat16* __restrict__ w1_l,
                __nv_bfloat16* __restrict__ w2_h, __nv_bfloat16* __restrict__ w2_l)
{
    const int i = blockIdx.x * 256 + threadIdx.x;
    if (i >= E_TOT) return;
    if (i < E_C1)      prep_one(Wi, BOND_FDIM,          HIDDEN,   KPAD_WI, wi_h, wi_l, i);
    else if (i < E_C2) prep_one(Wh, HIDDEN,             HIDDEN,   HIDDEN,  wh_h, wh_l, i - E_C1);
    else if (i < E_C3) prep_one(Wo, ATOM_FDIM + HIDDEN, HIDDEN,   KPAD_WO, wo_h, wo_l, i - E_C2);
    else if (i < E_C4) prep_one(W1, HIDDEN + MOL_FEAT,  FFNN_HID, KPAD_W1, w1_h, w1_l, i - E_C3);
    else               prep_one(W2, FFNN_HID,           ENC_HID,  KPAD_W2, w2_h, w2_l, i - E_C4);
}

// ---------------- neighbor-sum (float4, 8 atoms per 512-thread block) -------
__global__ __launch_bounds__(512)
void atom_agg_k(const float4* __restrict__ msg, const int* __restrict__ a2b,
                float4* __restrict__ amsg)
{
    const int a = blockIdx.x * 8 + (threadIdx.x >> 6);
    const int q = threadIdx.x & 63;
    const int* nb = a2b + (size_t)a * MAX_NB;
    int idx[MAX_NB];
    #pragma unroll
    for (int j = 0; j < MAX_NB; ++j) idx[j] = nb[j];
    float4 s = make_float4(0.f, 0.f, 0.f, 0.f);
    #pragma unroll
    for (int j = 0; j < MAX_NB; ++j) {
        const float4 v = msg[(size_t)idx[j] * 64 + q];
        s.x += v.x; s.y += v.y; s.z += v.z; s.w += v.w;
    }
    amsg[(size_t)a * 64 + q] = s;
}

// ---------------- segment mean + concat mol_features (stride 512, padded) ---
__global__ __launch_bounds__(256)
void mol_mean_k(const float* __restrict__ hid, const int* __restrict__ a2m,
                const float* __restrict__ mf, float* __restrict__ x)
{
    const int m = blockIdx.x;
    const int t = threadIdx.x;
    int lo = 0, hi = N_ATOMS;
    while (lo < hi) { int mid = (lo + hi) >> 1; if (a2m[mid] <  m) lo = mid + 1; else hi = mid; }
    const int start = lo;
    hi = N_ATOMS;
    while (lo < hi) { int mid = (lo + hi) >> 1; if (a2m[mid] <= m) lo = mid + 1; else hi = mid; }
    const int end = lo;

    float s = 0.f;
    for (int a = start; a < end; ++a) s += hid[(size_t)a * HIDDEN + t];
    const float cnt = (float)(end - start);
    x[(size_t)m * XSTRIDE + t] = s / fmaxf(cnt, 1.f);
    x[(size_t)m * XSTRIDE + HIDDEN + t] = (t < MOL_FEAT) ? mf[(size_t)m * MOL_FEAT + t] : 0.f;
}

// ---------------- launch -----------------------------------------------------
extern "C" void kernel_launch(void* const* d_in, const int* in_sizes, int n_in,
                              void* d_out, int out_size)
{
    const float* f_atoms      = (const float*)d_in[0];
    const float* f_bonds      = (const float*)d_in[1];
    const int*   a2b          = (const int*)  d_in[2];
    const int*   b2a          = (const int*)  d_in[3];
    const int*   b2revb       = (const int*)  d_in[4];
    const int*   atom2mol     = (const int*)  d_in[5];
    const float* mol_features = (const float*)d_in[6];
    const float* W_i          = (const float*)d_in[7];
    const float* W_h          = (const float*)d_in[8];
    const float* W_o_w        = (const float*)d_in[9];
    const float* W_o_b        = (const float*)d_in[10];
    const float* W1           = (const float*)d_in[11];
    const float* b1           = (const float*)d_in[12];
    const float* W2           = (const float*)d_in[13];
    const float* b2           = (const float*)d_in[14];
    float* out = (float*)d_out;

    float *inputs, *msgA, *msgB, *amsg, *hid, *x, *h;
    cudaGetSymbolAddress((void**)&inputs, g_inputs);
    cudaGetSymbolAddress((void**)&msgA,   g_msgA);
    cudaGetSymbolAddress((void**)&msgB,   g_msgB);
    cudaGetSymbolAddress((void**)&amsg,   g_amsg);
    cudaGetSymbolAddress((void**)&hid,    g_hid);
    cudaGetSymbolAddress((void**)&x,      g_x);
    cudaGetSymbolAddress((void**)&h,      g_h);

    __nv_bfloat16 *wi_h, *wi_l, *wh_h, *wh_l, *wo_h, *wo_l, *w1_h, *w1_l, *w2_h, *w2_l;
    cudaGetSymbolAddress((void**)&wi_h, g_Wi_hi); cudaGetSymbolAddress((void**)&wi_l, g_Wi_lo);
    cudaGetSymbolAddress((void**)&wh_h, g_Wh_hi); cudaGetSymbolAddress((void**)&wh_l, g_Wh_lo);
    cudaGetSymbolAddress((void**)&wo_h, g_Wo_hi); cudaGetSymbolAddress((void**)&wo_l, g_Wo_lo);
    cudaGetSymbolAddress((void**)&w1_h, g_W1_hi); cudaGetSymbolAddress((void**)&w1_l, g_W1_lo);
    cudaGetSymbolAddress((void**)&w2_h, g_W2_hi); cudaGetSymbolAddress((void**)&w2_l, g_W2_lo);

    cudaFuncSetAttribute((const void*)tgemm<MODE_PLAIN2, KPAD_WI / 32>, cudaFuncAttributeMaxDynamicSharedMemorySize, SMEM_TOT);
    cudaFuncSetAttribute((const void*)tgemm<MODE_MSG,    HIDDEN  / 32>, cudaFuncAttributeMaxDynamicSharedMemorySize, SMEM_TOT);
    cudaFuncSetAttribute((const void*)tgemm<MODE_CONCAT, KPAD_WO / 32>, cudaFuncAttributeMaxDynamicSharedMemorySize, SMEM_TOT);
    cudaFuncSetAttribute((const void*)tgemm<MODE_BIAS,   KPAD_W1 / 32>, cudaFuncAttributeMaxDynamicSharedMemorySize, SMEM_TOT);
    cudaFuncSetAttribute((const void*)tgemm<MODE_BIAS,   KPAD_W2 / 32>, cudaFuncAttributeMaxDynamicSharedMemorySize, SMEM_TOT);

    // ---- weight prep: single launch (keeps ncu -s window on hot kernels) ----
    prep_all_k<<<(E_TOT + 255) / 256, 256>>>(W_i, W_h, W_o_w, W1, W2,
                                             wi_h, wi_l, wh_h, wh_l, wo_h, wo_l,
                                             w1_h, w1_l, w2_h, w2_l);

    const int MB_BONDS = (N_BONDS + 63) / 64;   // 3125
    const int MB_ATOMS = (N_ATOMS + 63) / 64;   // 1563

    // 1) inputs = f_bonds @ W_i ; msgA = relu(inputs)
    tgemm<MODE_PLAIN2, KPAD_WI / 32><<<dim3(HIDDEN / 128, MB_BONDS), NTHR, SMEM_TOT>>>(
        f_bonds, BOND_FDIM, wi_h, wi_l, KPAD_WI,
        N_BONDS, HIDDEN, BOND_FDIM, inputs, msgA, nullptr, nullptr, nullptr, nullptr, nullptr);

    // 2) two message-passing iterations (double-buffered)
    float* cur = msgA;
    float* nxt = msgB;
    for (int d = 0; d < 2; ++d) {
        atom_agg_k<<<N_ATOMS / 8, 512>>>((const float4*)cur, a2b, (float4*)amsg);
        tgemm<MODE_MSG, HIDDEN / 32><<<dim3(HIDDEN / 128, MB_BONDS), NTHR, SMEM_TOT>>>(
            nullptr, 0, wh_h, wh_l, HIDDEN,
            N_BONDS, HIDDEN, HIDDEN, nxt, nullptr, inputs, b2a, b2revb, amsg, cur);
        float* t = cur; cur = nxt; nxt = t;
    }

    // 3) final aggregation + atom readout GEMM (fused concat)
    atom_agg_k<<<N_ATOMS / 8, 512>>>((const float4*)cur, a2b, (float4*)amsg);
    tgemm<MODE_CONCAT, KPAD_WO / 32><<<dim3(HIDDEN / 128, MB_ATOMS), NTHR, SMEM_TOT>>>(
        nullptr, 0, wo_h, wo_l, KPAD_WO,
        N_ATOMS, HIDDEN, ATOM_FDIM + HIDDEN, hid, nullptr, W_o_b, nullptr, nullptr, f_atoms, amsg);

    // 4) per-molecule mean + concat mol_features (padded to stride 512)
    mol_mean_k<<<N_MOLS, 256>>>(hid, atom2mol, mol_features, x);

    // 5) FFNN
    tgemm<MODE_BIAS, KPAD_W1 / 32><<<dim3(FFNN_HID / 128, N_MOLS / 64), NTHR, SMEM_TOT>>>(
        x, XSTRIDE, w1_h, w1_l, KPAD_W1,
        N_MOLS, FFNN_HID, KPAD_W1, h, nullptr, b1, nullptr, nullptr, nullptr, nullptr);
    tgemm<MODE_BIAS, KPAD_W2 / 32><<<dim3(ENC_HID / 128, N_MOLS / 64), NTHR, SMEM_TOT>>>(
        h, FFNN_HID, w2_h, w2_l, KPAD_W2,
        N_MOLS, ENC_HID, KPAD_W2, out, nullptr, b2, nullptr, nullptr, nullptr, nullptr);
}

// round 15
// speedup vs baseline: 1.3367x; 1.3367x over previous
#include <cuda_runtime.h>
#include <cuda_bf16.h>
#include <cstdint>

#define N_ATOMS   100000
#define N_BONDS   200000
#define MAX_NB    6
#define ATOM_FDIM 133
#define BOND_FDIM 147
#define HIDDEN    256
#define N_MOLS    4096
#define MOL_FEAT  200
#define FFNN_HID  512
#define ENC_HID   256

// K padded to multiple of 32 (chunk size)
#define KPAD_WI 160
#define KPAD_WO 416
#define KPAD_W1 480
#define KPAD_W2 512
#define XSTRIDE 512   // x buffer row stride (456 -> 512, zero filled)

// ---------------- scratch (static device globals; no allocation allowed) ----
__device__ float g_inputs[N_BONDS * HIDDEN];
__device__ float g_msgA  [N_BONDS * HIDDEN];
__device__ float g_msgB  [N_BONDS * HIDDEN];
__device__ float g_amsg  [N_ATOMS * HIDDEN];
__device__ float g_hid   [N_ATOMS * HIDDEN];
__device__ float g_x     [N_MOLS * XSTRIDE];
__device__ float g_h     [N_MOLS * FFNN_HID];

// split-bf16 weight buffers, layout [N][Kpad] (transposed, zero padded)
__device__ __nv_bfloat16 g_Wi_hi[HIDDEN  * KPAD_WI], g_Wi_lo[HIDDEN  * KPAD_WI];
__device__ __nv_bfloat16 g_Wh_hi[HIDDEN  * HIDDEN ], g_Wh_lo[HIDDEN  * HIDDEN ];
__device__ __nv_bfloat16 g_Wo_hi[HIDDEN  * KPAD_WO], g_Wo_lo[HIDDEN  * KPAD_WO];
__device__ __nv_bfloat16 g_W1_hi[FFNN_HID* KPAD_W1], g_W1_lo[FFNN_HID* KPAD_W1];
__device__ __nv_bfloat16 g_W2_hi[ENC_HID * KPAD_W2], g_W2_lo[ENC_HID * KPAD_W2];

// =================== PTX helpers (sm_80-level features only) ================
__device__ __forceinline__ uint32_t smem_u32(const void* p) {
    uint32_t a;
    asm("{ .reg .u64 t; cvta.to.shared.u64 t, %1; cvt.u32.u64 %0, t; }" : "=r"(a) : "l"(p));
    return a;
}
__device__ __forceinline__ void ldsm_x4(uint32_t* r, uint32_t addr) {
    asm volatile("ldmatrix.sync.aligned.m8n8.x4.shared.b16 {%0,%1,%2,%3}, [%4];"
                 : "=r"(r[0]), "=r"(r[1]), "=r"(r[2]), "=r"(r[3]) : "r"(addr));
}
__device__ __forceinline__ void mma16816(float* c, const uint32_t* a, uint32_t b0, uint32_t b1) {
    asm volatile("mma.sync.aligned.m16n8k16.row.col.f32.bf16.bf16.f32 "
                 "{%0,%1,%2,%3}, {%4,%5,%6,%7}, {%8,%9}, {%0,%1,%2,%3};"
                 : "+f"(c[0]), "+f"(c[1]), "+f"(c[2]), "+f"(c[3])
                 : "r"(a[0]), "r"(a[1]), "r"(a[2]), "r"(a[3]), "r"(b0), "r"(b1));
}
#define CP_ASYNC16(dst, src) \
    asm volatile("cp.async.cg.shared.global [%0], [%1], 16;" :: "r"(dst), "l"(src))
#define CP_COMMIT asm volatile("cp.async.commit_group;" ::: "memory")
#define CP_WAIT0  asm volatile("cp.async.wait_group 0;"  ::: "memory")

// 16B-slot swizzle: slot' = slot ^ ((row>>1)&3). Conflict-free for both the
// 8-row ldmatrix phases (even rows cover banks 0-15 with distinct slots, odd
// rows banks 16-31) and the 8-row x 4-seg staging stores.
__device__ __forceinline__ uint32_t sw_off(uint32_t row, uint32_t seg) {
    return row * 64u + ((seg ^ ((row >> 1) & 3u)) << 4);
}

// =================== tensor-core GEMM (mma.sync / HMMA), pipelined =========
// CTA: 256 thr, tile M=64 x N=128, K chunk 32. Split-bf16: hi*hi + lo*hi + hi*lo.
// Swizzled 64B rows (24.6KB/stage); 3 CTAs/SM (natural ~80 regs, no spills);
// 150KB smem/SM leaves a 78KB L1D carveout for the MSG gathers.
enum GemmMode { MODE_PLAIN2 = 0, MODE_MSG = 1, MODE_CONCAT = 2, MODE_BIAS = 3 };

#define A_ROWS   64
#define B_ROWS   128
#define OFF_I1   0
#define OFF_I2   256
#define STG_A_LO (A_ROWS * 64)                   // 4096
#define STG_B_HI (2 * A_ROWS * 64)               // 8192
#define STG_B_LO (STG_B_HI + B_ROWS * 64)        // 16384
#define STG_SZ   (STG_B_HI + 2 * B_ROWS * 64)    // 24576 bytes per stage
#define STG_BASE 1024
#define SMEM_TOT (STG_BASE + 2 * STG_SZ)         // 50176 bytes
#define NTHR 256

__device__ __forceinline__ void split_pack2(float x, float y, uint32_t& h, uint32_t& l) {
    __nv_bfloat16 hx = __float2bfloat16(x);
    __nv_bfloat16 hy = __float2bfloat16(y);
    __nv_bfloat16 lx = __float2bfloat16(x - __bfloat162float(hx));
    __nv_bfloat16 ly = __float2bfloat16(y - __bfloat162float(hy));
    h = (uint32_t)reinterpret_cast<unsigned short&>(hx) |
        ((uint32_t)reinterpret_cast<unsigned short&>(hy) << 16);
    l = (uint32_t)reinterpret_cast<unsigned short&>(lx) |
        ((uint32_t)reinterpret_cast<unsigned short&>(ly) << 16);
}

template<int MODE>
__device__ __forceinline__ void loadA_regs(float v[8], int gm, int kb, int M, int Ktrue,
                                           const float* __restrict__ A, int lda,
                                           const float* __restrict__ aux1,
                                           const float* __restrict__ aux2,
                                           int i1, int i2)
{
    if (MODE == MODE_MSG) {
        const float* p1 = aux1 + (size_t)i1 * HIDDEN + kb;
        const float* p2 = aux2 + (size_t)i2 * HIDDEN + kb;
        float4 a0 = *(const float4*)p1, a1 = *(const float4*)(p1 + 4);
        float4 b0 = *(const float4*)p2, b1 = *(const float4*)(p2 + 4);
        v[0]=a0.x-b0.x; v[1]=a0.y-b0.y; v[2]=a0.z-b0.z; v[3]=a0.w-b0.w;
        v[4]=a1.x-b1.x; v[5]=a1.y-b1.y; v[6]=a1.z-b1.z; v[7]=a1.w-b1.w;
    } else if (MODE == MODE_CONCAT) {
        #pragma unroll
        for (int j = 0; j < 8; ++j) {
            const int gk = kb + j;
            float x = 0.f;
            if (gm < M) {
                if (gk < ATOM_FDIM)               x = aux1[(size_t)gm * ATOM_FDIM + gk];
                else if (gk < ATOM_FDIM + HIDDEN) x = aux2[(size_t)gm * HIDDEN + (gk - ATOM_FDIM)];
            }
            v[j] = x;
        }
    } else if (MODE == MODE_BIAS) {
        const float* p = A + (size_t)gm * lda + kb;   // M multiple of 64, lda aligned
        float4 a0 = *(const float4*)p, a1 = *(const float4*)(p + 4);
        v[0]=a0.x; v[1]=a0.y; v[2]=a0.z; v[3]=a0.w;
        v[4]=a1.x; v[5]=a1.y; v[6]=a1.z; v[7]=a1.w;
    } else {  // MODE_PLAIN2 (f_bonds: ragged rows, unaligned stride)
        #pragma unroll
        for (int j = 0; j < 8; ++j) {
            const int gk = kb + j;
            v[j] = (gm < M && gk < Ktrue) ? A[(size_t)gm * lda + gk] : 0.f;
        }
    }
}

__device__ __forceinline__ void storeA_sm(char* smc, uint32_t stg, int arow, int aseg,
                                          const float v[8])
{
    uint32_t h[4], l[4];
    split_pack2(v[0], v[1], h[0], l[0]);
    split_pack2(v[2], v[3], h[1], l[1]);
    split_pack2(v[4], v[5], h[2], l[2]);
    split_pack2(v[6], v[7], h[3], l[3]);
    const uint32_t so = sw_off((uint32_t)arow, (uint32_t)aseg);
    *(uint4*)(smc + stg + so)            = make_uint4(h[0], h[1], h[2], h[3]);
    *(uint4*)(smc + stg + STG_A_LO + so) = make_uint4(l[0], l[1], l[2], l[3]);
}

__device__ __forceinline__ void loadB_cp(uint32_t sb_stg, const __nv_bfloat16* __restrict__ Bhi,
                                         const __nv_bfloat16* __restrict__ Blo,
                                         int n0, int Kpad, int k0, int tid)
{
    #pragma unroll
    for (int it = 0; it < 2; ++it) {
        const int t   = tid + it * NTHR;
        const int row = t >> 2, seg = t & 3;
        const size_t src = (size_t)(n0 + row) * Kpad + k0 + seg * 8;
        const uint32_t dst = sb_stg + STG_B_HI + sw_off((uint32_t)row, (uint32_t)seg);
        CP_ASYNC16(dst, Bhi + src);
        CP_ASYNC16(dst + (STG_B_LO - STG_B_HI), Blo + src);
    }
}

template<int MODE, int NCHUNKS>
__global__ __launch_bounds__(NTHR, 3)
void tgemm(const float* __restrict__ A, int lda,
           const __nv_bfloat16* __restrict__ Bhi, const __nv_bfloat16* __restrict__ Blo,
           int Kpad, int M, int Ntot, int Ktrue,
           float* __restrict__ C, float* __restrict__ C2,
           const float* __restrict__ ep,
           const int* __restrict__ idx1, const int* __restrict__ idx2,
           const float* __restrict__ aux1, const float* __restrict__ aux2)
{
    extern __shared__ char smc[];
    const uint32_t sb = smem_u32(smc);

    const int tid   = threadIdx.x;
    const int wid   = tid >> 5;
    const int lane  = tid & 31;
    const int warpM = wid & 1;          // 0..1 (M dir, 32 rows each)
    const int warpN = wid >> 1;         // 0..3 (N dir, 32 cols each)
    const int m0    = blockIdx.y * 64;
    const int n0    = blockIdx.x * 128;

    int* s_i1 = (int*)(smc + OFF_I1);
    int* s_i2 = (int*)(smc + OFF_I2);
    if (MODE == MODE_MSG && tid < 64) {
        int r = m0 + tid;
        s_i1[tid] = (r < M) ? idx1[r] : 0;
        s_i2[tid] = (r < M) ? idx2[r] : 0;
    }
    __syncthreads();

    const int arow_s = tid >> 2;        // staging A: row 0..63
    const int aseg   = tid & 3;         // seg 0..3 (8 elements each)
    const int gmA    = m0 + arow_s;
    int i1 = 0, i2 = 0;
    if (MODE == MODE_MSG) { i1 = s_i1[arow_s]; i2 = s_i2[arow_s]; }

    float acc[2][4][4];
    #pragma unroll
    for (int a = 0; a < 2; ++a)
        #pragma unroll
        for (int b = 0; b < 4; ++b)
            #pragma unroll
            for (int c = 0; c < 4; ++c) acc[a][b][c] = 0.f;

    // ---- prologue: stage chunk 0 into buffer 0 ----
    {
        loadB_cp(sb + STG_BASE, Bhi, Blo, n0, Kpad, 0, tid);
        CP_COMMIT;
        float v[8];
        loadA_regs<MODE>(v, gmA, aseg * 8, M, Ktrue, A, lda, aux1, aux2, i1, i2);
        storeA_sm(smc, STG_BASE, arow_s, aseg, v);
        CP_WAIT0;
        __syncthreads();
    }

    const uint32_t lrow = lane & 15;
    const uint32_t lkh  = (lane >> 4);          // 0..1: second 16B column

    #pragma unroll
    for (int ch = 0; ch < NCHUNKS; ++ch) {
        const int s = ch & 1;
        const uint32_t cur = STG_BASE + s * STG_SZ;
        const uint32_t nxt = STG_BASE + (s ^ 1) * STG_SZ;
        const bool more = (ch + 1 < NCHUNKS);   // compile-time after unroll

        // ---- prefetch next chunk: B via cp.async, A into registers ----
        float vn[8];
        if (more) {
            loadB_cp(sb + nxt, Bhi, Blo, n0, Kpad, (ch + 1) * 32, tid);
            CP_COMMIT;
            loadA_regs<MODE>(vn, gmA, (ch + 1) * 32 + aseg * 8, M, Ktrue,
                             A, lda, aux1, aux2, i1, i2);
        }

        // ---- compute on current stage: 2 x k16 ----
        #pragma unroll
        for (int kh = 0; kh < 2; ++kh) {
            const uint32_t segA = kh * 2 + lkh;   // 16B-slot index 0..3

            uint32_t ah[2][4], al[2][4];
            #pragma unroll
            for (int mt = 0; mt < 2; ++mt) {
                const uint32_t ao = sw_off(warpM * 32 + mt * 16 + lrow, segA);
                ldsm_x4(ah[mt], sb + cur + ao);
                ldsm_x4(al[mt], sb + cur + STG_A_LO + ao);
            }
            #pragma unroll
            for (int np = 0; np < 2; ++np) {
                const uint32_t bo = sw_off(warpN * 32 + np * 16 + lrow, segA);
                uint32_t b[4];
                // pass 1+2 use B_hi; pass 3 reuses the same regs for B_lo
                ldsm_x4(b, sb + cur + STG_B_HI + bo);
                #pragma unroll
                for (int mt = 0; mt < 2; ++mt) {
                    mma16816(acc[mt][2*np    ], ah[mt], b[0], b[2]);
                    mma16816(acc[mt][2*np + 1], ah[mt], b[1], b[3]);
                }
                #pragma unroll
                for (int mt = 0; mt < 2; ++mt) {
                    mma16816(acc[mt][2*np    ], al[mt], b[0], b[2]);
                    mma16816(acc[mt][2*np + 1], al[mt], b[1], b[3]);
                }
                ldsm_x4(b, sb + cur + STG_B_LO + bo);
                #pragma unroll
                for (int mt = 0; mt < 2; ++mt) {
                    mma16816(acc[mt][2*np    ], ah[mt], b[0], b[2]);
                    mma16816(acc[mt][2*np + 1], ah[mt], b[1], b[3]);
                }
            }
        }

        // ---- finish staging next chunk ----
        if (more) {
            storeA_sm(smc, nxt, arow_s, aseg, vn);
            CP_WAIT0;
            __syncthreads();
        }
    }

    // ---- epilogue: direct accumulator stores with fused ops ----
    const int gi = lane >> 2;    // 0..7
    const int qi = lane & 3;     // 0..3
    #pragma unroll
    for (int mt = 0; mt < 2; ++mt) {
        const int row0 = m0 + warpM * 32 + mt * 16 + gi;
        #pragma unroll
        for (int nt = 0; nt < 4; ++nt) {
            const int gn = n0 + warpN * 32 + nt * 8 + qi * 2;
            const float* c = acc[mt][nt];
            #pragma unroll
            for (int half = 0; half < 2; ++half) {
                const int gm = row0 + half * 8;
                if (gm >= M) continue;
                const float u0 = c[2 * half], u1 = c[2 * half + 1];
                const size_t co = (size_t)gm * Ntot + gn;
                if (MODE == MODE_PLAIN2) {
                    *(float2*)(C  + co) = make_float2(u0, u1);
                    *(float2*)(C2 + co) = make_float2(fmaxf(u0, 0.f), fmaxf(u1, 0.f));
                } else if (MODE == MODE_MSG) {
                    const float2 e = *(const float2*)(ep + co);
                    *(float2*)(C + co) = make_float2(fmaxf(u0 + e.x, 0.f), fmaxf(u1 + e.y, 0.f));
                } else {
                    const float2 e = *(const float2*)(ep + gn);
                    *(float2*)(C + co) = make_float2(fmaxf(u0 + e.x, 0.f), fmaxf(u1 + e.y, 0.f));
                }
            }
        }
    }
}

// ---------------- merged weight prep: ONE launch for all 5 weights ---------
__device__ __forceinline__ void prep_one(const float* __restrict__ W, int K, int N, int Kpad,
                                         __nv_bfloat16* __restrict__ hi,
                                         __nv_bfloat16* __restrict__ lo, int i)
{
    const int n = i / Kpad, k = i % Kpad;
    const float v = (k < K) ? W[(size_t)k * N + n] : 0.f;
    const __nv_bfloat16 h = __float2bfloat16(v);
    hi[i] = h;
    lo[i] = __float2bfloat16(v - __bfloat162float(h));
}

#define E_WI (HIDDEN  * KPAD_WI)                  // 40960
#define E_WH (HIDDEN  * HIDDEN)                   // 65536
#define E_WO (HIDDEN  * KPAD_WO)                  // 106496
#define E_W1 (FFNN_HID* KPAD_W1)                  // 245760
#define E_W2 (ENC_HID * KPAD_W2)                  // 131072
#define E_C1 (E_WI)
#define E_C2 (E_C1 + E_WH)
#define E_C3 (E_C2 + E_WO)
#define E_C4 (E_C3 + E_W1)
#define E_TOT (E_C4 + E_W2)                       // 589824

__global__ __launch_bounds__(256)
void prep_all_k(const float* __restrict__ Wi, const float* __restrict__ Wh,
                const float* __restrict__ Wo, const float* __restrict__ W1,
                const float* __restrict__ W2,
                __nv_bfloat16* __restrict__ wi_h, __nv_bfloat16* __restrict__ wi_l,
                __nv_bfloat16* __restrict__ wh_h, __nv_bfloat16* __restrict__ wh_l,
                __nv_bfloat16* __restrict__ wo_h, __nv_bfloat16* __restrict__ wo_l,
                __nv_bfloat16* __restrict__ w1_h, __nv_bfloat16* __restrict__ w1_l,
                __nv_bfloat16* __restrict__ w2_h, __nv_bfloat16* __restrict__ w2_l)
{
    const int i = blockIdx.x * 256 + threadIdx.x;
    if (i >= E_TOT) return;
    if (i < E_C1)      prep_one(Wi, BOND_FDIM,          HIDDEN,   KPAD_WI, wi_h, wi_l, i);
    else if (i < E_C2) prep_one(Wh, HIDDEN,             HIDDEN,   HIDDEN,  wh_h, wh_l, i - E_C1);
    else if (i < E_C3) prep_one(Wo, ATOM_FDIM + HIDDEN, HIDDEN,   KPAD_WO, wo_h, wo_l, i - E_C2);
    else if (i < E_C4) prep_one(W1, HIDDEN + MOL_FEAT,  FFNN_HID, KPAD_W1, w1_h, w1_l, i - E_C3);
    else               prep_one(W2, FFNN_HID,           ENC_HID,  KPAD_W2, w2_h, w2_l, i - E_C4);
}

// ---------------- neighbor-sum (float4, 8 atoms per 512-thread block) -------
__global__ __launch_bounds__(512)
void atom_agg_k(const float4* __restrict__ msg, const int* __restrict__ a2b,
                float4* __restrict__ amsg)
{
    const int a = blockIdx.x * 8 + (threadIdx.x >> 6);
    const int q = threadIdx.x & 63;
    const int* nb = a2b + (size_t)a * MAX_NB;
    int idx[MAX_NB];
    #pragma unroll
    for (int j = 0; j < MAX_NB; ++j) idx[j] = nb[j];
    float4 s = make_float4(0.f, 0.f, 0.f, 0.f);
    #pragma unroll
    for (int j = 0; j < MAX_NB; ++j) {
        const float4 v = msg[(size_t)idx[j] * 64 + q];
        s.x += v.x; s.y += v.y; s.z += v.z; s.w += v.w;
    }
    amsg[(size_t)a * 64 + q] = s;
}

// ---------------- segment mean + concat mol_features (stride 512, padded) ---
__global__ __launch_bounds__(256)
void mol_mean_k(const float* __restrict__ hid, const int* __restrict__ a2m,
                const float* __restrict__ mf, float* __restrict__ x)
{
    const int m = blockIdx.x;
    const int t = threadIdx.x;
    int lo = 0, hi = N_ATOMS;
    while (lo < hi) { int mid = (lo + hi) >> 1; if (a2m[mid] <  m) lo = mid + 1; else hi = mid; }
    const int start = lo;
    hi = N_ATOMS;
    while (lo < hi) { int mid = (lo + hi) >> 1; if (a2m[mid] <= m) lo = mid + 1; else hi = mid; }
    const int end = lo;

    float s = 0.f;
    for (int a = start; a < end; ++a) s += hid[(size_t)a * HIDDEN + t];
    const float cnt = (float)(end - start);
    x[(size_t)m * XSTRIDE + t] = s / fmaxf(cnt, 1.f);
    x[(size_t)m * XSTRIDE + HIDDEN + t] = (t < MOL_FEAT) ? mf[(size_t)m * MOL_FEAT + t] : 0.f;
}

// ---------------- launch -----------------------------------------------------
extern "C" void kernel_launch(void* const* d_in, const int* in_sizes, int n_in,
                              void* d_out, int out_size)
{
    const float* f_atoms      = (const float*)d_in[0];
    const float* f_bonds      = (const float*)d_in[1];
    const int*   a2b          = (const int*)  d_in[2];
    const int*   b2a          = (const int*)  d_in[3];
    const int*   b2revb       = (const int*)  d_in[4];
    const int*   atom2mol     = (const int*)  d_in[5];
    const float* mol_features = (const float*)d_in[6];
    const float* W_i          = (const float*)d_in[7];
    const float* W_h          = (const float*)d_in[8];
    const float* W_o_w        = (const float*)d_in[9];
    const float* W_o_b        = (const float*)d_in[10];
    const float* W1           = (const float*)d_in[11];
    const float* b1           = (const float*)d_in[12];
    const float* W2           = (const float*)d_in[13];
    const float* b2           = (const float*)d_in[14];
    float* out = (float*)d_out;

    float *inputs, *msgA, *msgB, *amsg, *hid, *x, *h;
    cudaGetSymbolAddress((void**)&inputs, g_inputs);
    cudaGetSymbolAddress((void**)&msgA,   g_msgA);
    cudaGetSymbolAddress((void**)&msgB,   g_msgB);
    cudaGetSymbolAddress((void**)&amsg,   g_amsg);
    cudaGetSymbolAddress((void**)&hid,    g_hid);
    cudaGetSymbolAddress((void**)&x,      g_x);
    cudaGetSymbolAddress((void**)&h,      g_h);

    __nv_bfloat16 *wi_h, *wi_l, *wh_h, *wh_l, *wo_h, *wo_l, *w1_h, *w1_l, *w2_h, *w2_l;
    cudaGetSymbolAddress((void**)&wi_h, g_Wi_hi); cudaGetSymbolAddress((void**)&wi_l, g_Wi_lo);
    cudaGetSymbolAddress((void**)&wh_h, g_Wh_hi); cudaGetSymbolAddress((void**)&wh_l, g_Wh_lo);
    cudaGetSymbolAddress((void**)&wo_h, g_Wo_hi); cudaGetSymbolAddress((void**)&wo_l, g_Wo_lo);
    cudaGetSymbolAddress((void**)&w1_h, g_W1_hi); cudaGetSymbolAddress((void**)&w1_l, g_W1_lo);
    cudaGetSymbolAddress((void**)&w2_h, g_W2_hi); cudaGetSymbolAddress((void**)&w2_l, g_W2_lo);

    cudaFuncSetAttribute((const void*)tgemm<MODE_PLAIN2, KPAD_WI / 32>, cudaFuncAttributeMaxDynamicSharedMemorySize, SMEM_TOT);
    cudaFuncSetAttribute((const void*)tgemm<MODE_MSG,    HIDDEN  / 32>, cudaFuncAttributeMaxDynamicSharedMemorySize, SMEM_TOT);
    cudaFuncSetAttribute((const void*)tgemm<MODE_CONCAT, KPAD_WO / 32>, cudaFuncAttributeMaxDynamicSharedMemorySize, SMEM_TOT);
    cudaFuncSetAttribute((const void*)tgemm<MODE_BIAS,   KPAD_W1 / 32>, cudaFuncAttributeMaxDynamicSharedMemorySize, SMEM_TOT);
    cudaFuncSetAttribute((const void*)tgemm<MODE_BIAS,   KPAD_W2 / 32>, cudaFuncAttributeMaxDynamicSharedMemorySize, SMEM_TOT);

    // ---- weight prep: single launch (keeps ncu -s window on hot kernels) ----
    prep_all_k<<<(E_TOT + 255) / 256, 256>>>(W_i, W_h, W_o_w, W1, W2,
                                             wi_h, wi_l, wh_h, wh_l, wo_h, wo_l,
                                             w1_h, w1_l, w2_h, w2_l);

    const int MB_BONDS = (N_BONDS + 63) / 64;   // 3125
    const int MB_ATOMS = (N_ATOMS + 63) / 64;   // 1563

    // 1) inputs = f_bonds @ W_i ; msgA = relu(inputs)
    tgemm<MODE_PLAIN2, KPAD_WI / 32><<<dim3(HIDDEN / 128, MB_BONDS), NTHR, SMEM_TOT>>>(
        f_bonds, BOND_FDIM, wi_h, wi_l, KPAD_WI,
        N_BONDS, HIDDEN, BOND_FDIM, inputs, msgA, nullptr, nullptr, nullptr, nullptr, nullptr);

    // 2) two message-passing iterations (double-buffered)
    float* cur = msgA;
    float* nxt = msgB;
    for (int d = 0; d < 2; ++d) {
        atom_agg_k<<<N_ATOMS / 8, 512>>>((const float4*)cur, a2b, (float4*)amsg);
        tgemm<MODE_MSG, HIDDEN / 32><<<dim3(HIDDEN / 128, MB_BONDS), NTHR, SMEM_TOT>>>(
            nullptr, 0, wh_h, wh_l, HIDDEN,
            N_BONDS, HIDDEN, HIDDEN, nxt, nullptr, inputs, b2a, b2revb, amsg, cur);
        float* t = cur; cur = nxt; nxt = t;
    }

    // 3) final aggregation + atom readout GEMM (fused concat)
    atom_agg_k<<<N_ATOMS / 8, 512>>>((const float4*)cur, a2b, (float4*)amsg);
    tgemm<MODE_CONCAT, KPAD_WO / 32><<<dim3(HIDDEN / 128, MB_ATOMS), NTHR, SMEM_TOT>>>(
        nullptr, 0, wo_h, wo_l, KPAD_WO,
        N_ATOMS, HIDDEN, ATOM_FDIM + HIDDEN, hid, nullptr, W_o_b, nullptr, nullptr, f_atoms, amsg);

    // 4) per-molecule mean + concat mol_features (padded to stride 512)
    mol_mean_k<<<N_MOLS, 256>>>(hid, atom2mol, mol_features, x);

    // 5) FFNN
    tgemm<MODE_BIAS, KPAD_W1 / 32><<<dim3(FFNN_HID / 128, N_MOLS / 64), NTHR, SMEM_TOT>>>(
        x, XSTRIDE, w1_h, w1_l, KPAD_W1,
        N_MOLS, FFNN_HID, KPAD_W1, h, nullptr, b1, nullptr, nullptr, nullptr, nullptr);
    tgemm<MODE_BIAS, KPAD_W2 / 32><<<dim3(ENC_HID / 128, N_MOLS / 64), NTHR, SMEM_TOT>>>(
        h, FFNN_HID, w2_h, w2_l, KPAD_W2,
        N_MOLS, ENC_HID, KPAD_W2, out, nullptr, b2, nullptr, nullptr, nullptr, nullptr);
}

// round 16
// speedup vs baseline: 1.3383x; 1.0012x over previous
#include <cuda_runtime.h>
#include <cuda_bf16.h>
#include <cstdint>

#define N_ATOMS   100000
#define N_BONDS   200000
#define MAX_NB    6
#define ATOM_FDIM 133
#define BOND_FDIM 147
#define HIDDEN    256
#define N_MOLS    4096
#define MOL_FEAT  200
#define FFNN_HID  512
#define ENC_HID   256

// K padded to multiple of 32 (chunk size)
#define KPAD_WI 160
#define KPAD_WO 416
#define KPAD_W1 480
#define KPAD_W2 512
#define XSTRIDE 512   // x buffer row stride (456 -> 512, zero filled)

// ---------------- scratch (static device globals; no allocation allowed) ----
__device__ float g_inputs[N_BONDS * HIDDEN];
__device__ float g_msgA  [N_BONDS * HIDDEN];
__device__ float g_msgB  [N_BONDS * HIDDEN];
__device__ float g_amsg  [N_ATOMS * HIDDEN];
__device__ float g_hid   [N_ATOMS * HIDDEN];
__device__ float g_x     [N_MOLS * XSTRIDE];
__device__ float g_h     [N_MOLS * FFNN_HID];

// split-bf16 weight buffers, layout [N][Kpad] (transposed, zero padded)
__device__ __nv_bfloat16 g_Wi_hi[HIDDEN  * KPAD_WI], g_Wi_lo[HIDDEN  * KPAD_WI];
__device__ __nv_bfloat16 g_Wh_hi[HIDDEN  * HIDDEN ], g_Wh_lo[HIDDEN  * HIDDEN ];
__device__ __nv_bfloat16 g_Wo_hi[HIDDEN  * KPAD_WO], g_Wo_lo[HIDDEN  * KPAD_WO];
__device__ __nv_bfloat16 g_W1_hi[FFNN_HID* KPAD_W1], g_W1_lo[FFNN_HID* KPAD_W1];
__device__ __nv_bfloat16 g_W2_hi[ENC_HID * KPAD_W2], g_W2_lo[ENC_HID * KPAD_W2];

// =================== PTX helpers (sm_80-level features only) ================
__device__ __forceinline__ uint32_t smem_u32(const void* p) {
    uint32_t a;
    asm("{ .reg .u64 t; cvta.to.shared.u64 t, %1; cvt.u32.u64 %0, t; }" : "=r"(a) : "l"(p));
    return a;
}
__device__ __forceinline__ void ldsm_x4(uint32_t* r, uint32_t addr) {
    asm volatile("ldmatrix.sync.aligned.m8n8.x4.shared.b16 {%0,%1,%2,%3}, [%4];"
                 : "=r"(r[0]), "=r"(r[1]), "=r"(r[2]), "=r"(r[3]) : "r"(addr));
}
__device__ __forceinline__ void mma16816(float* c, const uint32_t* a, uint32_t b0, uint32_t b1) {
    asm volatile("mma.sync.aligned.m16n8k16.row.col.f32.bf16.bf16.f32 "
                 "{%0,%1,%2,%3}, {%4,%5,%6,%7}, {%8,%9}, {%0,%1,%2,%3};"
                 : "+f"(c[0]), "+f"(c[1]), "+f"(c[2]), "+f"(c[3])
                 : "r"(a[0]), "r"(a[1]), "r"(a[2]), "r"(a[3]), "r"(b0), "r"(b1));
}
#define CP_ASYNC16(dst, src) \
    asm volatile("cp.async.cg.shared.global [%0], [%1], 16;" :: "r"(dst), "l"(src))
#define CP_COMMIT asm volatile("cp.async.commit_group;" ::: "memory")
#define CP_WAIT0  asm volatile("cp.async.wait_group 0;"  ::: "memory")

// 16B-slot swizzle: slot' = slot ^ ((row>>1)&3). Conflict-free for the 8-row
// ldmatrix phases and the staging stores (validated R15).
__device__ __forceinline__ uint32_t sw_off(uint32_t row, uint32_t seg) {
    return row * 64u + ((seg ^ ((row >> 1) & 3u)) << 4);
}

// =================== tensor-core GEMM (mma.sync / HMMA), pipelined =========
// CTA: 256 thr, tile M=64 x N=256, warp grid 2Mx4N (warp tile 32x64).
// K chunk 32. Split-bf16: hi*hi + lo*hi + hi*lo. Swizzled 64B rows.
// 2 CTAs/SM; smem reads 48KB per 64x128-unit (25% less than N=128 config);
// grid.x=1 for N=256 outputs halves the A-gather DRAM traffic.
enum GemmMode { MODE_PLAIN2 = 0, MODE_MSG = 1, MODE_CONCAT = 2, MODE_BIAS = 3 };

#define A_ROWS   64
#define B_ROWS   256
#define OFF_I1   0
#define OFF_I2   256
#define STG_A_LO (A_ROWS * 64)                   // 4096
#define STG_B_HI (2 * A_ROWS * 64)               // 8192
#define STG_B_LO (STG_B_HI + B_ROWS * 64)        // 24576
#define STG_SZ   (STG_B_HI + 2 * B_ROWS * 64)    // 40960 bytes per stage
#define STG_BASE 1024
#define SMEM_TOT (STG_BASE + 2 * STG_SZ)         // 82944 bytes -> 2 CTAs/SM
#define NTHR 256

__device__ __forceinline__ void split_pack2(float x, float y, uint32_t& h, uint32_t& l) {
    __nv_bfloat16 hx = __float2bfloat16(x);
    __nv_bfloat16 hy = __float2bfloat16(y);
    __nv_bfloat16 lx = __float2bfloat16(x - __bfloat162float(hx));
    __nv_bfloat16 ly = __float2bfloat16(y - __bfloat162float(hy));
    h = (uint32_t)reinterpret_cast<unsigned short&>(hx) |
        ((uint32_t)reinterpret_cast<unsigned short&>(hy) << 16);
    l = (uint32_t)reinterpret_cast<unsigned short&>(lx) |
        ((uint32_t)reinterpret_cast<unsigned short&>(ly) << 16);
}

template<int MODE>
__device__ __forceinline__ void loadA_regs(float v[8], int gm, int kb, int M, int Ktrue,
                                           const float* __restrict__ A, int lda,
                                           const float* __restrict__ aux1,
                                           const float* __restrict__ aux2,
                                           int i1, int i2)
{
    if (MODE == MODE_MSG) {
        const float* p1 = aux1 + (size_t)i1 * HIDDEN + kb;
        const float* p2 = aux2 + (size_t)i2 * HIDDEN + kb;
        float4 a0 = *(const float4*)p1, a1 = *(const float4*)(p1 + 4);
        float4 b0 = *(const float4*)p2, b1 = *(const float4*)(p2 + 4);
        v[0]=a0.x-b0.x; v[1]=a0.y-b0.y; v[2]=a0.z-b0.z; v[3]=a0.w-b0.w;
        v[4]=a1.x-b1.x; v[5]=a1.y-b1.y; v[6]=a1.z-b1.z; v[7]=a1.w-b1.w;
    } else if (MODE == MODE_CONCAT) {
        #pragma unroll
        for (int j = 0; j < 8; ++j) {
            const int gk = kb + j;
            float x = 0.f;
            if (gm < M) {
                if (gk < ATOM_FDIM)               x = aux1[(size_t)gm * ATOM_FDIM + gk];
                else if (gk < ATOM_FDIM + HIDDEN) x = aux2[(size_t)gm * HIDDEN + (gk - ATOM_FDIM)];
            }
            v[j] = x;
        }
    } else if (MODE == MODE_BIAS) {
        const float* p = A + (size_t)gm * lda + kb;   // M multiple of 64, lda aligned
        float4 a0 = *(const float4*)p, a1 = *(const float4*)(p + 4);
        v[0]=a0.x; v[1]=a0.y; v[2]=a0.z; v[3]=a0.w;
        v[4]=a1.x; v[5]=a1.y; v[6]=a1.z; v[7]=a1.w;
    } else {  // MODE_PLAIN2 (f_bonds: ragged rows, unaligned stride)
        #pragma unroll
        for (int j = 0; j < 8; ++j) {
            const int gk = kb + j;
            v[j] = (gm < M && gk < Ktrue) ? A[(size_t)gm * lda + gk] : 0.f;
        }
    }
}

__device__ __forceinline__ void storeA_sm(char* smc, uint32_t stg, int arow, int aseg,
                                          const float v[8])
{
    uint32_t h[4], l[4];
    split_pack2(v[0], v[1], h[0], l[0]);
    split_pack2(v[2], v[3], h[1], l[1]);
    split_pack2(v[4], v[5], h[2], l[2]);
    split_pack2(v[6], v[7], h[3], l[3]);
    const uint32_t so = sw_off((uint32_t)arow, (uint32_t)aseg);
    *(uint4*)(smc + stg + so)            = make_uint4(h[0], h[1], h[2], h[3]);
    *(uint4*)(smc + stg + STG_A_LO + so) = make_uint4(l[0], l[1], l[2], l[3]);
}

__device__ __forceinline__ void loadB_cp(uint32_t sb_stg, const __nv_bfloat16* __restrict__ Bhi,
                                         const __nv_bfloat16* __restrict__ Blo,
                                         int n0, int Kpad, int k0, int tid)
{
    #pragma unroll
    for (int it = 0; it < 4; ++it) {
        const int t   = tid + it * NTHR;
        const int row = t >> 2, seg = t & 3;
        const size_t src = (size_t)(n0 + row) * Kpad + k0 + seg * 8;
        const uint32_t dst = sb_stg + STG_B_HI + sw_off((uint32_t)row, (uint32_t)seg);
        CP_ASYNC16(dst, Bhi + src);
        CP_ASYNC16(dst + (STG_B_LO - STG_B_HI), Blo + src);
    }
}

template<int MODE, int NCHUNKS>
__global__ __launch_bounds__(NTHR, 2)
void tgemm(const float* __restrict__ A, int lda,
           const __nv_bfloat16* __restrict__ Bhi, const __nv_bfloat16* __restrict__ Blo,
           int Kpad, int M, int Ntot, int Ktrue,
           float* __restrict__ C, float* __restrict__ C2,
           const float* __restrict__ ep,
           const int* __restrict__ idx1, const int* __restrict__ idx2,
           const float* __restrict__ aux1, const float* __restrict__ aux2)
{
    extern __shared__ char smc[];
    const uint32_t sb = smem_u32(smc);

    const int tid   = threadIdx.x;
    const int wid   = tid >> 5;
    const int lane  = tid & 31;
    const int warpM = wid & 1;          // 0..1 (M dir, 32 rows each)
    const int warpN = wid >> 1;         // 0..3 (N dir, 64 cols each)
    const int m0    = blockIdx.y * 64;
    const int n0    = blockIdx.x * 256;

    int* s_i1 = (int*)(smc + OFF_I1);
    int* s_i2 = (int*)(smc + OFF_I2);
    if (MODE == MODE_MSG && tid < 64) {
        int r = m0 + tid;
        s_i1[tid] = (r < M) ? idx1[r] : 0;
        s_i2[tid] = (r < M) ? idx2[r] : 0;
    }
    __syncthreads();

    const int arow_s = tid >> 2;        // staging A: row 0..63
    const int aseg   = tid & 3;         // seg 0..3 (8 elements each)
    const int gmA    = m0 + arow_s;
    int i1 = 0, i2 = 0;
    if (MODE == MODE_MSG) { i1 = s_i1[arow_s]; i2 = s_i2[arow_s]; }

    float acc[2][8][4];
    #pragma unroll
    for (int a = 0; a < 2; ++a)
        #pragma unroll
        for (int b = 0; b < 8; ++b)
            #pragma unroll
            for (int c = 0; c < 4; ++c) acc[a][b][c] = 0.f;

    // ---- prologue: stage chunk 0 into buffer 0 ----
    {
        loadB_cp(sb + STG_BASE, Bhi, Blo, n0, Kpad, 0, tid);
        CP_COMMIT;
        float v[8];
        loadA_regs<MODE>(v, gmA, aseg * 8, M, Ktrue, A, lda, aux1, aux2, i1, i2);
        storeA_sm(smc, STG_BASE, arow_s, aseg, v);
        CP_WAIT0;
        __syncthreads();
    }

    const uint32_t lrow = lane & 15;
    const uint32_t lkh  = (lane >> 4);          // 0..1: second 16B column

    #pragma unroll
    for (int ch = 0; ch < NCHUNKS; ++ch) {
        const int s = ch & 1;
        const uint32_t cur = STG_BASE + s * STG_SZ;
        const uint32_t nxt = STG_BASE + (s ^ 1) * STG_SZ;
        const bool more = (ch + 1 < NCHUNKS);   // compile-time after unroll

        // ---- prefetch next chunk: B via cp.async, A into registers ----
        float vn[8];
        if (more) {
            loadB_cp(sb + nxt, Bhi, Blo, n0, Kpad, (ch + 1) * 32, tid);
            CP_COMMIT;
            loadA_regs<MODE>(vn, gmA, (ch + 1) * 32 + aseg * 8, M, Ktrue,
                             A, lda, aux1, aux2, i1, i2);
        }

        // ---- compute on current stage: 2 x k16 ----
        #pragma unroll
        for (int kh = 0; kh < 2; ++kh) {
            const uint32_t segA = kh * 2 + lkh;   // 16B-slot index 0..3

            uint32_t ah[2][4], al[2][4];
            #pragma unroll
            for (int mt = 0; mt < 2; ++mt) {
                const uint32_t ao = sw_off(warpM * 32 + mt * 16 + lrow, segA);
                ldsm_x4(ah[mt], sb + cur + ao);
                ldsm_x4(al[mt], sb + cur + STG_A_LO + ao);
            }
            #pragma unroll
            for (int np = 0; np < 4; ++np) {
                const uint32_t bo = sw_off(warpN * 64 + np * 16 + lrow, segA);
                uint32_t b[4];
                // pass 1+2 use B_hi; pass 3 reuses the same regs for B_lo
                ldsm_x4(b, sb + cur + STG_B_HI + bo);
                #pragma unroll
                for (int mt = 0; mt < 2; ++mt) {
                    mma16816(acc[mt][2*np    ], ah[mt], b[0], b[2]);
                    mma16816(acc[mt][2*np + 1], ah[mt], b[1], b[3]);
                }
                #pragma unroll
                for (int mt = 0; mt < 2; ++mt) {
                    mma16816(acc[mt][2*np    ], al[mt], b[0], b[2]);
                    mma16816(acc[mt][2*np + 1], al[mt], b[1], b[3]);
                }
                ldsm_x4(b, sb + cur + STG_B_LO + bo);
                #pragma unroll
                for (int mt = 0; mt < 2; ++mt) {
                    mma16816(acc[mt][2*np    ], ah[mt], b[0], b[2]);
                    mma16816(acc[mt][2*np + 1], ah[mt], b[1], b[3]);
                }
            }
        }

        // ---- finish staging next chunk ----
        if (more) {
            storeA_sm(smc, nxt, arow_s, aseg, vn);
            CP_WAIT0;
            __syncthreads();
        }
    }

    // ---- epilogue: direct accumulator stores with fused ops ----
    const int gi = lane >> 2;    // 0..7
    const int qi = lane & 3;     // 0..3
    #pragma unroll
    for (int mt = 0; mt < 2; ++mt) {
        const int row0 = m0 + warpM * 32 + mt * 16 + gi;
        #pragma unroll
        for (int nt = 0; nt < 8; ++nt) {
            const int gn = n0 + warpN * 64 + nt * 8 + qi * 2;
            const float* c = acc[mt][nt];
            #pragma unroll
            for (int half = 0; half < 2; ++half) {
                const int gm = row0 + half * 8;
                if (gm >= M) continue;
                const float u0 = c[2 * half], u1 = c[2 * half + 1];
                const size_t co = (size_t)gm * Ntot + gn;
                if (MODE == MODE_PLAIN2) {
                    *(float2*)(C  + co) = make_float2(u0, u1);
                    *(float2*)(C2 + co) = make_float2(fmaxf(u0, 0.f), fmaxf(u1, 0.f));
                } else if (MODE == MODE_MSG) {
                    const float2 e = *(const float2*)(ep + co);
                    *(float2*)(C + co) = make_float2(fmaxf(u0 + e.x, 0.f), fmaxf(u1 + e.y, 0.f));
                } else {
                    const float2 e = *(const float2*)(ep + gn);
                    *(float2*)(C + co) = make_float2(fmaxf(u0 + e.x, 0.f), fmaxf(u1 + e.y, 0.f));
                }
            }
        }
    }
}

// ---------------- merged weight prep: ONE launch for all 5 weights ---------
__device__ __forceinline__ void prep_one(const float* __restrict__ W, int K, int N, int Kpad,
                                         __nv_bfloat16* __restrict__ hi,
                                         __nv_bfloat16* __restrict__ lo, int i)
{
    const int n = i / Kpad, k = i % Kpad;
    const float v = (k < K) ? W[(size_t)k * N + n] : 0.f;
    const __nv_bfloat16 h = __float2bfloat16(v);
    hi[i] = h;
    lo[i] = __float2bfloat16(v - __bfloat162float(h));
}

#define E_WI (HIDDEN  * KPAD_WI)                  // 40960
#define E_WH (HIDDEN  * HIDDEN)                   // 65536
#define E_WO (HIDDEN  * KPAD_WO)                  // 106496
#define E_W1 (FFNN_HID* KPAD_W1)                  // 245760
#define E_W2 (ENC_HID * KPAD_W2)                  // 131072
#define E_C1 (E_WI)
#define E_C2 (E_C1 + E_WH)
#define E_C3 (E_C2 + E_WO)
#define E_C4 (E_C3 + E_W1)
#define E_TOT (E_C4 + E_W2)                       // 589824

__global__ __launch_bounds__(256)
void prep_all_k(const float* __restrict__ Wi, const float* __restrict__ Wh,
                const float* __restrict__ Wo, const float* __restrict__ W1,
                const float* __restrict__ W2,
                __nv_bfloat16* __restrict__ wi_h, __nv_bfloat16* __restrict__ wi_l,
                __nv_bfloat16* __restrict__ wh_h, __nv_bfloat16* __restrict__ wh_l,
                __nv_bfloat16* __restrict__ wo_h, __nv_bfloat16* __restrict__ wo_l,
                __nv_bfloat16* __restrict__ w1_h, __nv_bfloat16* __restrict__ w1_l,
                __nv_bfloat16* __restrict__ w2_h, __nv_bfloat16* __restrict__ w2_l)
{
    const int i = blockIdx.x * 256 + threadIdx.x;
    if (i >= E_TOT) return;
    if (i < E_C1)      prep_one(Wi, BOND_FDIM,          HIDDEN,   KPAD_WI, wi_h, wi_l, i);
    else if (i < E_C2) prep_one(Wh, HIDDEN,             HIDDEN,   HIDDEN,  wh_h, wh_l, i - E_C1);
    else if (i < E_C3) prep_one(Wo, ATOM_FDIM + HIDDEN, HIDDEN,   KPAD_WO, wo_h, wo_l, i - E_C2);
    else if (i < E_C4) prep_one(W1, HIDDEN + MOL_FEAT,  FFNN_HID, KPAD_W1, w1_h, w1_l, i - E_C3);
    else               prep_one(W2, FFNN_HID,           ENC_HID,  KPAD_W2, w2_h, w2_l, i - E_C4);
}

// ---------------- neighbor-sum (float4, 8 atoms per 512-thread block) -------
__global__ __launch_bounds__(512)
void atom_agg_k(const float4* __restrict__ msg, const int* __restrict__ a2b,
                float4* __restrict__ amsg)
{
    const int a = blockIdx.x * 8 + (threadIdx.x >> 6);
    const int q = threadIdx.x & 63;
    const int* nb = a2b + (size_t)a * MAX_NB;
    int idx[MAX_NB];
    #pragma unroll
    for (int j = 0; j < MAX_NB; ++j) idx[j] = nb[j];
    float4 s = make_float4(0.f, 0.f, 0.f, 0.f);
    #pragma unroll
    for (int j = 0; j < MAX_NB; ++j) {
        const float4 v = msg[(size_t)idx[j] * 64 + q];
        s.x += v.x; s.y += v.y; s.z += v.z; s.w += v.w;
    }
    amsg[(size_t)a * 64 + q] = s;
}

// ---------------- segment mean + concat mol_features (stride 512, padded) ---
__global__ __launch_bounds__(256)
void mol_mean_k(const float* __restrict__ hid, const int* __restrict__ a2m,
                const float* __restrict__ mf, float* __restrict__ x)
{
    const int m = blockIdx.x;
    const int t = threadIdx.x;
    int lo = 0, hi = N_ATOMS;
    while (lo < hi) { int mid = (lo + hi) >> 1; if (a2m[mid] <  m) lo = mid + 1; else hi = mid; }
    const int start = lo;
    hi = N_ATOMS;
    while (lo < hi) { int mid = (lo + hi) >> 1; if (a2m[mid] <= m) lo = mid + 1; else hi = mid; }
    const int end = lo;

    float s = 0.f;
    for (int a = start; a < end; ++a) s += hid[(size_t)a * HIDDEN + t];
    const float cnt = (float)(end - start);
    x[(size_t)m * XSTRIDE + t] = s / fmaxf(cnt, 1.f);
    x[(size_t)m * XSTRIDE + HIDDEN + t] = (t < MOL_FEAT) ? mf[(size_t)m * MOL_FEAT + t] : 0.f;
}

// ---------------- launch -----------------------------------------------------
extern "C" void kernel_launch(void* const* d_in, const int* in_sizes, int n_in,
                              void* d_out, int out_size)
{
    const float* f_atoms      = (const float*)d_in[0];
    const float* f_bonds      = (const float*)d_in[1];
    const int*   a2b          = (const int*)  d_in[2];
    const int*   b2a          = (const int*)  d_in[3];
    const int*   b2revb       = (const int*)  d_in[4];
    const int*   atom2mol     = (const int*)  d_in[5];
    const float* mol_features = (const float*)d_in[6];
    const float* W_i          = (const float*)d_in[7];
    const float* W_h          = (const float*)d_in[8];
    const float* W_o_w        = (const float*)d_in[9];
    const float* W_o_b        = (const float*)d_in[10];
    const float* W1           = (const float*)d_in[11];
    const float* b1           = (const float*)d_in[12];
    const float* W2           = (const float*)d_in[13];
    const float* b2           = (const float*)d_in[14];
    float* out = (float*)d_out;

    float *inputs, *msgA, *msgB, *amsg, *hid, *x, *h;
    cudaGetSymbolAddress((void**)&inputs, g_inputs);
    cudaGetSymbolAddress((void**)&msgA,   g_msgA);
    cudaGetSymbolAddress((void**)&msgB,   g_msgB);
    cudaGetSymbolAddress((void**)&amsg,   g_amsg);
    cudaGetSymbolAddress((void**)&hid,    g_hid);
    cudaGetSymbolAddress((void**)&x,      g_x);
    cudaGetSymbolAddress((void**)&h,      g_h);

    __nv_bfloat16 *wi_h, *wi_l, *wh_h, *wh_l, *wo_h, *wo_l, *w1_h, *w1_l, *w2_h, *w2_l;
    cudaGetSymbolAddress((void**)&wi_h, g_Wi_hi); cudaGetSymbolAddress((void**)&wi_l, g_Wi_lo);
    cudaGetSymbolAddress((void**)&wh_h, g_Wh_hi); cudaGetSymbolAddress((void**)&wh_l, g_Wh_lo);
    cudaGetSymbolAddress((void**)&wo_h, g_Wo_hi); cudaGetSymbolAddress((void**)&wo_l, g_Wo_lo);
    cudaGetSymbolAddress((void**)&w1_h, g_W1_hi); cudaGetSymbolAddress((void**)&w1_l, g_W1_lo);
    cudaGetSymbolAddress((void**)&w2_h, g_W2_hi); cudaGetSymbolAddress((void**)&w2_l, g_W2_lo);

    cudaFuncSetAttribute((const void*)tgemm<MODE_PLAIN2, KPAD_WI / 32>, cudaFuncAttributeMaxDynamicSharedMemorySize, SMEM_TOT);
    cudaFuncSetAttribute((const void*)tgemm<MODE_MSG,    HIDDEN  / 32>, cudaFuncAttributeMaxDynamicSharedMemorySize, SMEM_TOT);
    cudaFuncSetAttribute((const void*)tgemm<MODE_CONCAT, KPAD_WO / 32>, cudaFuncAttributeMaxDynamicSharedMemorySize, SMEM_TOT);
    cudaFuncSetAttribute((const void*)tgemm<MODE_BIAS,   KPAD_W1 / 32>, cudaFuncAttributeMaxDynamicSharedMemorySize, SMEM_TOT);
    cudaFuncSetAttribute((const void*)tgemm<MODE_BIAS,   KPAD_W2 / 32>, cudaFuncAttributeMaxDynamicSharedMemorySize, SMEM_TOT);

    // ---- weight prep: single launch (keeps ncu -s window on hot kernels) ----
    prep_all_k<<<(E_TOT + 255) / 256, 256>>>(W_i, W_h, W_o_w, W1, W2,
                                             wi_h, wi_l, wh_h, wh_l, wo_h, wo_l,
                                             w1_h, w1_l, w2_h, w2_l);

    const int MB_BONDS = (N_BONDS + 63) / 64;   // 3125
    const int MB_ATOMS = (N_ATOMS + 63) / 64;   // 1563

    // 1) inputs = f_bonds @ W_i ; msgA = relu(inputs)
    tgemm<MODE_PLAIN2, KPAD_WI / 32><<<dim3(1, MB_BONDS), NTHR, SMEM_TOT>>>(
        f_bonds, BOND_FDIM, wi_h, wi_l, KPAD_WI,
        N_BONDS, HIDDEN, BOND_FDIM, inputs, msgA, nullptr, nullptr, nullptr, nullptr, nullptr);

    // 2) two message-passing iterations (double-buffered)
    float* cur = msgA;
    float* nxt = msgB;
    for (int d = 0; d < 2; ++d) {
        atom_agg_k<<<N_ATOMS / 8, 512>>>((const float4*)cur, a2b, (float4*)amsg);
        tgemm<MODE_MSG, HIDDEN / 32><<<dim3(1, MB_BONDS), NTHR, SMEM_TOT>>>(
            nullptr, 0, wh_h, wh_l, HIDDEN,
            N_BONDS, HIDDEN, HIDDEN, nxt, nullptr, inputs, b2a, b2revb, amsg, cur);
        float* t = cur; cur = nxt; nxt = t;
    }

    // 3) final aggregation + atom readout GEMM (fused concat)
    atom_agg_k<<<N_ATOMS / 8, 512>>>((const float4*)cur, a2b, (float4*)amsg);
    tgemm<MODE_CONCAT, KPAD_WO / 32><<<dim3(1, MB_ATOMS), NTHR, SMEM_TOT>>>(
        nullptr, 0, wo_h, wo_l, KPAD_WO,
        N_ATOMS, HIDDEN, ATOM_FDIM + HIDDEN, hid, nullptr, W_o_b, nullptr, nullptr, f_atoms, amsg);

    // 4) per-molecule mean + concat mol_features (padded to stride 512)
    mol_mean_k<<<N_MOLS, 256>>>(hid, atom2mol, mol_features, x);

    // 5) FFNN
    tgemm<MODE_BIAS, KPAD_W1 / 32><<<dim3(FFNN_HID / 256, N_MOLS / 64), NTHR, SMEM_TOT>>>(
        x, XSTRIDE, w1_h, w1_l, KPAD_W1,
        N_MOLS, FFNN_HID, KPAD_W1, h, nullptr, b1, nullptr, nullptr, nullptr, nullptr);
    tgemm<MODE_BIAS, KPAD_W2 / 32><<<dim3(ENC_HID / 256, N_MOLS / 64), NTHR, SMEM_TOT>>>(
        h, FFNN_HID, w2_h, w2_l, KPAD_W2,
        N_MOLS, ENC_HID, KPAD_W2, out, nullptr, b2, nullptr, nullptr, nullptr, nullptr);
}

// round 17
// speedup vs baseline: 1.6390x; 1.2247x over previous
#include <cuda_runtime.h>
#include <cuda_fp16.h>
#include <cstdint>

#define N_ATOMS   100000
#define N_BONDS   200000
#define MAX_NB    6
#define ATOM_FDIM 133
#define BOND_FDIM 147
#define HIDDEN    256
#define N_MOLS    4096
#define MOL_FEAT  200
#define FFNN_HID  512
#define ENC_HID   256

// K padded to multiple of 32 (chunk size)
#define KPAD_WI 160
#define KPAD_WO 416
#define KPAD_W1 480
#define KPAD_W2 512
#define XSTRIDE 512   // x buffer row stride (456 -> 512, zero filled)

// ---------------- scratch (static device globals; no allocation allowed) ----
__device__ float g_inputs[N_BONDS * HIDDEN];
__device__ float g_msgA  [N_BONDS * HIDDEN];
__device__ float g_msgB  [N_BONDS * HIDDEN];
__device__ float g_amsg  [N_ATOMS * HIDDEN];
__device__ float g_hid   [N_ATOMS * HIDDEN];
__device__ float g_x     [N_MOLS * XSTRIDE];
__device__ float g_h     [N_MOLS * FFNN_HID];

// fp16 weight buffers, layout [N][Kpad] (transposed, zero padded, single copy)
__device__ __half g_Wi[HIDDEN  * KPAD_WI];
__device__ __half g_Wh[HIDDEN  * HIDDEN ];
__device__ __half g_Wo[HIDDEN  * KPAD_WO];
__device__ __half g_W1[FFNN_HID* KPAD_W1];
__device__ __half g_W2[ENC_HID * KPAD_W2];

// =================== PTX helpers (sm_80-level features only) ================
__device__ __forceinline__ uint32_t smem_u32(const void* p) {
    uint32_t a;
    asm("{ .reg .u64 t; cvta.to.shared.u64 t, %1; cvt.u32.u64 %0, t; }" : "=r"(a) : "l"(p));
    return a;
}
__device__ __forceinline__ void ldsm_x4(uint32_t* r, uint32_t addr) {
    asm volatile("ldmatrix.sync.aligned.m8n8.x4.shared.b16 {%0,%1,%2,%3}, [%4];"
                 : "=r"(r[0]), "=r"(r[1]), "=r"(r[2]), "=r"(r[3]) : "r"(addr));
}
__device__ __forceinline__ void mma16816(float* c, const uint32_t* a, uint32_t b0, uint32_t b1) {
    asm volatile("mma.sync.aligned.m16n8k16.row.col.f32.f16.f16.f32 "
                 "{%0,%1,%2,%3}, {%4,%5,%6,%7}, {%8,%9}, {%0,%1,%2,%3};"
                 : "+f"(c[0]), "+f"(c[1]), "+f"(c[2]), "+f"(c[3])
                 : "r"(a[0]), "r"(a[1]), "r"(a[2]), "r"(a[3]), "r"(b0), "r"(b1));
}
#define CP_ASYNC16(dst, src) \
    asm volatile("cp.async.cg.shared.global [%0], [%1], 16;" :: "r"(dst), "l"(src))
#define CP_COMMIT asm volatile("cp.async.commit_group;" ::: "memory")
#define CP_WAIT0  asm volatile("cp.async.wait_group 0;"  ::: "memory")

// 16B-slot swizzle: slot' = slot ^ ((row>>1)&3). Conflict-free for the 8-row
// ldmatrix phases and the staging stores (validated R15).
__device__ __forceinline__ uint32_t sw_off(uint32_t row, uint32_t seg) {
    return row * 64u + ((seg ^ ((row >> 1) & 3u)) << 4);
}

// =================== tensor-core GEMM (mma.sync / HMMA), pipelined =========
// CTA: 256 thr, tile M=64 x N=256, warp grid 2Mx4N (warp tile 32x64).
// K chunk 32. fp16 2-pass: A = A_hi + A_lo (fp16 split, near-exact),
// B = single fp16 (only error source, ~2^-12). 33% fewer mma + ldsm than
// the bf16 3-pass scheme; B smem/DRAM traffic halved.
enum GemmMode { MODE_PLAIN2 = 0, MODE_MSG = 1, MODE_CONCAT = 2, MODE_BIAS = 3 };

#define A_ROWS   64
#define B_ROWS   256
#define OFF_I1   0
#define OFF_I2   256
#define STG_A_LO (A_ROWS * 64)                   // 4096
#define STG_B    (2 * A_ROWS * 64)               // 8192
#define STG_SZ   (STG_B + B_ROWS * 64)           // 24576 bytes per stage
#define STG_BASE 1024
#define SMEM_TOT (STG_BASE + 2 * STG_SZ)         // 50176 bytes
#define NTHR 256

__device__ __forceinline__ void split_pack2h(float x, float y, uint32_t& h, uint32_t& l) {
    __half hx = __float2half_rn(x);
    __half hy = __float2half_rn(y);
    __half lx = __float2half_rn(x - __half2float(hx));
    __half ly = __float2half_rn(y - __half2float(hy));
    h = (uint32_t)reinterpret_cast<unsigned short&>(hx) |
        ((uint32_t)reinterpret_cast<unsigned short&>(hy) << 16);
    l = (uint32_t)reinterpret_cast<unsigned short&>(lx) |
        ((uint32_t)reinterpret_cast<unsigned short&>(ly) << 16);
}

template<int MODE>
__device__ __forceinline__ void loadA_regs(float v[8], int gm, int kb, int M, int Ktrue,
                                           const float* __restrict__ A, int lda,
                                           const float* __restrict__ aux1,
                                           const float* __restrict__ aux2,
                                           int i1, int i2)
{
    if (MODE == MODE_MSG) {
        const float* p1 = aux1 + (size_t)i1 * HIDDEN + kb;
        const float* p2 = aux2 + (size_t)i2 * HIDDEN + kb;
        float4 a0 = *(const float4*)p1, a1 = *(const float4*)(p1 + 4);
        float4 b0 = *(const float4*)p2, b1 = *(const float4*)(p2 + 4);
        v[0]=a0.x-b0.x; v[1]=a0.y-b0.y; v[2]=a0.z-b0.z; v[3]=a0.w-b0.w;
        v[4]=a1.x-b1.x; v[5]=a1.y-b1.y; v[6]=a1.z-b1.z; v[7]=a1.w-b1.w;
    } else if (MODE == MODE_CONCAT) {
        #pragma unroll
        for (int j = 0; j < 8; ++j) {
            const int gk = kb + j;
            float x = 0.f;
            if (gm < M) {
                if (gk < ATOM_FDIM)               x = aux1[(size_t)gm * ATOM_FDIM + gk];
                else if (gk < ATOM_FDIM + HIDDEN) x = aux2[(size_t)gm * HIDDEN + (gk - ATOM_FDIM)];
            }
            v[j] = x;
        }
    } else if (MODE == MODE_BIAS) {
        const float* p = A + (size_t)gm * lda + kb;   // M multiple of 64, lda aligned
        float4 a0 = *(const float4*)p, a1 = *(const float4*)(p + 4);
        v[0]=a0.x; v[1]=a0.y; v[2]=a0.z; v[3]=a0.w;
        v[4]=a1.x; v[5]=a1.y; v[6]=a1.z; v[7]=a1.w;
    } else {  // MODE_PLAIN2 (f_bonds: ragged rows, unaligned stride)
        #pragma unroll
        for (int j = 0; j < 8; ++j) {
            const int gk = kb + j;
            v[j] = (gm < M && gk < Ktrue) ? A[(size_t)gm * lda + gk] : 0.f;
        }
    }
}

__device__ __forceinline__ void storeA_sm(char* smc, uint32_t stg, int arow, int aseg,
                                          const float v[8])
{
    uint32_t h[4], l[4];
    split_pack2h(v[0], v[1], h[0], l[0]);
    split_pack2h(v[2], v[3], h[1], l[1]);
    split_pack2h(v[4], v[5], h[2], l[2]);
    split_pack2h(v[6], v[7], h[3], l[3]);
    const uint32_t so = sw_off((uint32_t)arow, (uint32_t)aseg);
    *(uint4*)(smc + stg + so)            = make_uint4(h[0], h[1], h[2], h[3]);
    *(uint4*)(smc + stg + STG_A_LO + so) = make_uint4(l[0], l[1], l[2], l[3]);
}

__device__ __forceinline__ void loadB_cp(uint32_t sb_stg, const __half* __restrict__ B,
                                         int n0, int Kpad, int k0, int tid)
{
    #pragma unroll
    for (int it = 0; it < 4; ++it) {
        const int t   = tid + it * NTHR;
        const int row = t >> 2, seg = t & 3;
        const size_t src = (size_t)(n0 + row) * Kpad + k0 + seg * 8;
        const uint32_t dst = sb_stg + STG_B + sw_off((uint32_t)row, (uint32_t)seg);
        CP_ASYNC16(dst, B + src);
    }
}

template<int MODE, int NCHUNKS>
__global__ __launch_bounds__(NTHR, 2)
void tgemm(const float* __restrict__ A, int lda,
           const __half* __restrict__ B,
           int Kpad, int M, int Ntot, int Ktrue,
           float* __restrict__ C, float* __restrict__ C2,
           const float* __restrict__ ep,
           const int* __restrict__ idx1, const int* __restrict__ idx2,
           const float* __restrict__ aux1, const float* __restrict__ aux2)
{
    extern __shared__ char smc[];
    const uint32_t sb = smem_u32(smc);

    const int tid   = threadIdx.x;
    const int wid   = tid >> 5;
    const int lane  = tid & 31;
    const int warpM = wid & 1;          // 0..1 (M dir, 32 rows each)
    const int warpN = wid >> 1;         // 0..3 (N dir, 64 cols each)
    const int m0    = blockIdx.y * 64;
    const int n0    = blockIdx.x * 256;

    int* s_i1 = (int*)(smc + OFF_I1);
    int* s_i2 = (int*)(smc + OFF_I2);
    if (MODE == MODE_MSG && tid < 64) {
        int r = m0 + tid;
        s_i1[tid] = (r < M) ? idx1[r] : 0;
        s_i2[tid] = (r < M) ? idx2[r] : 0;
    }
    __syncthreads();

    const int arow_s = tid >> 2;        // staging A: row 0..63
    const int aseg   = tid & 3;         // seg 0..3 (8 elements each)
    const int gmA    = m0 + arow_s;
    int i1 = 0, i2 = 0;
    if (MODE == MODE_MSG) { i1 = s_i1[arow_s]; i2 = s_i2[arow_s]; }

    float acc[2][8][4];
    #pragma unroll
    for (int a = 0; a < 2; ++a)
        #pragma unroll
        for (int b = 0; b < 8; ++b)
            #pragma unroll
            for (int c = 0; c < 4; ++c) acc[a][b][c] = 0.f;

    // ---- prologue: stage chunk 0 into buffer 0 ----
    {
        loadB_cp(sb + STG_BASE, B, n0, Kpad, 0, tid);
        CP_COMMIT;
        float v[8];
        loadA_regs<MODE>(v, gmA, aseg * 8, M, Ktrue, A, lda, aux1, aux2, i1, i2);
        storeA_sm(smc, STG_BASE, arow_s, aseg, v);
        CP_WAIT0;
        __syncthreads();
    }

    const uint32_t lrow = lane & 15;
    const uint32_t lkh  = (lane >> 4);          // 0..1: second 16B column

    #pragma unroll
    for (int ch = 0; ch < NCHUNKS; ++ch) {
        const int s = ch & 1;
        const uint32_t cur = STG_BASE + s * STG_SZ;
        const uint32_t nxt = STG_BASE + (s ^ 1) * STG_SZ;
        const bool more = (ch + 1 < NCHUNKS);   // compile-time after unroll

        // ---- prefetch next chunk: B via cp.async, A into registers ----
        float vn[8];
        if (more) {
            loadB_cp(sb + nxt, B, n0, Kpad, (ch + 1) * 32, tid);
            CP_COMMIT;
            loadA_regs<MODE>(vn, gmA, (ch + 1) * 32 + aseg * 8, M, Ktrue,
                             A, lda, aux1, aux2, i1, i2);
        }

        // ---- compute on current stage: 2 x k16, 2 passes (A_hi, A_lo) ----
        #pragma unroll
        for (int kh = 0; kh < 2; ++kh) {
            const uint32_t segA = kh * 2 + lkh;   // 16B-slot index 0..3

            uint32_t ah[2][4], al[2][4];
            #pragma unroll
            for (int mt = 0; mt < 2; ++mt) {
                const uint32_t ao = sw_off(warpM * 32 + mt * 16 + lrow, segA);
                ldsm_x4(ah[mt], sb + cur + ao);
                ldsm_x4(al[mt], sb + cur + STG_A_LO + ao);
            }
            #pragma unroll
            for (int np = 0; np < 4; ++np) {
                const uint32_t bo = sw_off(warpN * 64 + np * 16 + lrow, segA);
                uint32_t b[4];
                ldsm_x4(b, sb + cur + STG_B + bo);
                #pragma unroll
                for (int mt = 0; mt < 2; ++mt) {
                    mma16816(acc[mt][2*np    ], ah[mt], b[0], b[2]);
                    mma16816(acc[mt][2*np + 1], ah[mt], b[1], b[3]);
                }
                #pragma unroll
                for (int mt = 0; mt < 2; ++mt) {
                    mma16816(acc[mt][2*np    ], al[mt], b[0], b[2]);
                    mma16816(acc[mt][2*np + 1], al[mt], b[1], b[3]);
                }
            }
        }

        // ---- finish staging next chunk ----
        if (more) {
            storeA_sm(smc, nxt, arow_s, aseg, vn);
            CP_WAIT0;
            __syncthreads();
        }
    }

    // ---- epilogue: direct accumulator stores with fused ops ----
    const int gi = lane >> 2;    // 0..7
    const int qi = lane & 3;     // 0..3
    #pragma unroll
    for (int mt = 0; mt < 2; ++mt) {
        const int row0 = m0 + warpM * 32 + mt * 16 + gi;
        #pragma unroll
        for (int nt = 0; nt < 8; ++nt) {
            const int gn = n0 + warpN * 64 + nt * 8 + qi * 2;
            const float* c = acc[mt][nt];
            #pragma unroll
            for (int half = 0; half < 2; ++half) {
                const int gm = row0 + half * 8;
                if (gm >= M) continue;
                const float u0 = c[2 * half], u1 = c[2 * half + 1];
                const size_t co = (size_t)gm * Ntot + gn;
                if (MODE == MODE_PLAIN2) {
                    *(float2*)(C  + co) = make_float2(u0, u1);
                    *(float2*)(C2 + co) = make_float2(fmaxf(u0, 0.f), fmaxf(u1, 0.f));
                } else if (MODE == MODE_MSG) {
                    const float2 e = *(const float2*)(ep + co);
                    *(float2*)(C + co) = make_float2(fmaxf(u0 + e.x, 0.f), fmaxf(u1 + e.y, 0.f));
                } else {
                    const float2 e = *(const float2*)(ep + gn);
                    *(float2*)(C + co) = make_float2(fmaxf(u0 + e.x, 0.f), fmaxf(u1 + e.y, 0.f));
                }
            }
        }
    }
}

// ---------------- merged weight prep: ONE launch for all 5 weights ---------
__device__ __forceinline__ void prep_one(const float* __restrict__ W, int K, int N, int Kpad,
                                         __half* __restrict__ out, int i)
{
    const int n = i / Kpad, k = i % Kpad;
    const float v = (k < K) ? W[(size_t)k * N + n] : 0.f;
    out[i] = __float2half_rn(v);
}

#define E_WI (HIDDEN  * KPAD_WI)                  // 40960
#define E_WH (HIDDEN  * HIDDEN)                   // 65536
#define E_WO (HIDDEN  * KPAD_WO)                  // 106496
#define E_W1 (FFNN_HID* KPAD_W1)                  // 245760
#define E_W2 (ENC_HID * KPAD_W2)                  // 131072
#define E_C1 (E_WI)
#define E_C2 (E_C1 + E_WH)
#define E_C3 (E_C2 + E_WO)
#define E_C4 (E_C3 + E_W1)
#define E_TOT (E_C4 + E_W2)                       // 589824

__global__ __launch_bounds__(256)
void prep_all_k(const float* __restrict__ Wi, const float* __restrict__ Wh,
                const float* __restrict__ Wo, const float* __restrict__ W1,
                const float* __restrict__ W2,
                __half* __restrict__ wi, __half* __restrict__ wh,
                __half* __restrict__ wo, __half* __restrict__ w1,
                __half* __restrict__ w2)
{
    const int i = blockIdx.x * 256 + threadIdx.x;
    if (i >= E_TOT) return;
    if (i < E_C1)      prep_one(Wi, BOND_FDIM,          HIDDEN,   KPAD_WI, wi, i);
    else if (i < E_C2) prep_one(Wh, HIDDEN,             HIDDEN,   HIDDEN,  wh, i - E_C1);
    else if (i < E_C3) prep_one(Wo, ATOM_FDIM + HIDDEN, HIDDEN,   KPAD_WO, wo, i - E_C2);
    else if (i < E_C4) prep_one(W1, HIDDEN + MOL_FEAT,  FFNN_HID, KPAD_W1, w1, i - E_C3);
    else               prep_one(W2, FFNN_HID,           ENC_HID,  KPAD_W2, w2, i - E_C4);
}

// ---------------- neighbor-sum (float4, 8 atoms per 512-thread block) -------
__global__ __launch_bounds__(512)
void atom_agg_k(const float4* __restrict__ msg, const int* __restrict__ a2b,
                float4* __restrict__ amsg)
{
    const int a = blockIdx.x * 8 + (threadIdx.x >> 6);
    const int q = threadIdx.x & 63;
    const int* nb = a2b + (size_t)a * MAX_NB;
    int idx[MAX_NB];
    #pragma unroll
    for (int j = 0; j < MAX_NB; ++j) idx[j] = nb[j];
    float4 s = make_float4(0.f, 0.f, 0.f, 0.f);
    #pragma unroll
    for (int j = 0; j < MAX_NB; ++j) {
        const float4 v = msg[(size_t)idx[j] * 64 + q];
        s.x += v.x; s.y += v.y; s.z += v.z; s.w += v.w;
    }
    amsg[(size_t)a * 64 + q] = s;
}

// ---------------- segment mean + concat mol_features (stride 512, padded) ---
__global__ __launch_bounds__(256)
void mol_mean_k(const float* __restrict__ hid, const int* __restrict__ a2m,
                const float* __restrict__ mf, float* __restrict__ x)
{
    const int m = blockIdx.x;
    const int t = threadIdx.x;
    int lo = 0, hi = N_ATOMS;
    while (lo < hi) { int mid = (lo + hi) >> 1; if (a2m[mid] <  m) lo = mid + 1; else hi = mid; }
    const int start = lo;
    hi = N_ATOMS;
    while (lo < hi) { int mid = (lo + hi) >> 1; if (a2m[mid] <= m) lo = mid + 1; else hi = mid; }
    const int end = lo;

    float s = 0.f;
    for (int a = start; a < end; ++a) s += hid[(size_t)a * HIDDEN + t];
    const float cnt = (float)(end - start);
    x[(size_t)m * XSTRIDE + t] = s / fmaxf(cnt, 1.f);
    x[(size_t)m * XSTRIDE + HIDDEN + t] = (t < MOL_FEAT) ? mf[(size_t)m * MOL_FEAT + t] : 0.f;
}

// ---------------- launch -----------------------------------------------------
extern "C" void kernel_launch(void* const* d_in, const int* in_sizes, int n_in,
                              void* d_out, int out_size)
{
    const float* f_atoms      = (const float*)d_in[0];
    const float* f_bonds      = (const float*)d_in[1];
    const int*   a2b          = (const int*)  d_in[2];
    const int*   b2a          = (const int*)  d_in[3];
    const int*   b2revb       = (const int*)  d_in[4];
    const int*   atom2mol     = (const int*)  d_in[5];
    const float* mol_features = (const float*)d_in[6];
    const float* W_i          = (const float*)d_in[7];
    const float* W_h          = (const float*)d_in[8];
    const float* W_o_w        = (const float*)d_in[9];
    const float* W_o_b        = (const float*)d_in[10];
    const float* W1           = (const float*)d_in[11];
    const float* b1           = (const float*)d_in[12];
    const float* W2           = (const float*)d_in[13];
    const float* b2           = (const float*)d_in[14];
    float* out = (float*)d_out;

    float *inputs, *msgA, *msgB, *amsg, *hid, *x, *h;
    cudaGetSymbolAddress((void**)&inputs, g_inputs);
    cudaGetSymbolAddress((void**)&msgA,   g_msgA);
    cudaGetSymbolAddress((void**)&msgB,   g_msgB);
    cudaGetSymbolAddress((void**)&amsg,   g_amsg);
    cudaGetSymbolAddress((void**)&hid,    g_hid);
    cudaGetSymbolAddress((void**)&x,      g_x);
    cudaGetSymbolAddress((void**)&h,      g_h);

    __half *wi, *wh, *wo, *w1, *w2;
    cudaGetSymbolAddress((void**)&wi, g_Wi);
    cudaGetSymbolAddress((void**)&wh, g_Wh);
    cudaGetSymbolAddress((void**)&wo, g_Wo);
    cudaGetSymbolAddress((void**)&w1, g_W1);
    cudaGetSymbolAddress((void**)&w2, g_W2);

    cudaFuncSetAttribute((const void*)tgemm<MODE_PLAIN2, KPAD_WI / 32>, cudaFuncAttributeMaxDynamicSharedMemorySize, SMEM_TOT);
    cudaFuncSetAttribute((const void*)tgemm<MODE_MSG,    HIDDEN  / 32>, cudaFuncAttributeMaxDynamicSharedMemorySize, SMEM_TOT);
    cudaFuncSetAttribute((const void*)tgemm<MODE_CONCAT, KPAD_WO / 32>, cudaFuncAttributeMaxDynamicSharedMemorySize, SMEM_TOT);
    cudaFuncSetAttribute((const void*)tgemm<MODE_BIAS,   KPAD_W1 / 32>, cudaFuncAttributeMaxDynamicSharedMemorySize, SMEM_TOT);
    cudaFuncSetAttribute((const void*)tgemm<MODE_BIAS,   KPAD_W2 / 32>, cudaFuncAttributeMaxDynamicSharedMemorySize, SMEM_TOT);

    // ---- weight prep: single launch ----
    prep_all_k<<<(E_TOT + 255) / 256, 256>>>(W_i, W_h, W_o_w, W1, W2,
                                             wi, wh, wo, w1, w2);

    const int MB_BONDS = (N_BONDS + 63) / 64;   // 3125
    const int MB_ATOMS = (N_ATOMS + 63) / 64;   // 1563

    // 1) inputs = f_bonds @ W_i ; msgA = relu(inputs)
    tgemm<MODE_PLAIN2, KPAD_WI / 32><<<dim3(1, MB_BONDS), NTHR, SMEM_TOT>>>(
        f_bonds, BOND_FDIM, wi, KPAD_WI,
        N_BONDS, HIDDEN, BOND_FDIM, inputs, msgA, nullptr, nullptr, nullptr, nullptr, nullptr);

    // 2) two message-passing iterations (double-buffered)
    float* cur = msgA;
    float* nxt = msgB;
    for (int d = 0; d < 2; ++d) {
        atom_agg_k<<<N_ATOMS / 8, 512>>>((const float4*)cur, a2b, (float4*)amsg);
        tgemm<MODE_MSG, HIDDEN / 32><<<dim3(1, MB_BONDS), NTHR, SMEM_TOT>>>(
            nullptr, 0, wh, HIDDEN,
            N_BONDS, HIDDEN, HIDDEN, nxt, nullptr, inputs, b2a, b2revb, amsg, cur);
        float* t = cur; cur = nxt; nxt = t;
    }

    // 3) final aggregation + atom readout GEMM (fused concat)
    atom_agg_k<<<N_ATOMS / 8, 512>>>((const float4*)cur, a2b, (float4*)amsg);
    tgemm<MODE_CONCAT, KPAD_WO / 32><<<dim3(1, MB_ATOMS), NTHR, SMEM_TOT>>>(
        nullptr, 0, wo, KPAD_WO,
        N_ATOMS, HIDDEN, ATOM_FDIM + HIDDEN, hid, nullptr, W_o_b, nullptr, nullptr, f_atoms, amsg);

    // 4) per-molecule mean + concat mol_features (padded to stride 512)
    mol_mean_k<<<N_MOLS, 256>>>(hid, atom2mol, mol_features, x);

    // 5) FFNN
    tgemm<MODE_BIAS, KPAD_W1 / 32><<<dim3(FFNN_HID / 256, N_MOLS / 64), NTHR, SMEM_TOT>>>(
        x, XSTRIDE, w1, KPAD_W1,
        N_MOLS, FFNN_HID, KPAD_W1, h, nullptr, b1, nullptr, nullptr, nullptr, nullptr);
    tgemm<MODE_BIAS, KPAD_W2 / 32><<<dim3(ENC_HID / 256, N_MOLS / 64), NTHR, SMEM_TOT>>>(
        h, FFNN_HID, w2, KPAD_W2,
        N_MOLS, ENC_HID, KPAD_W2, out, nullptr, b2, nullptr, nullptr, nullptr, nullptr);
}